// round 9
// baseline (speedup 1.0000x reference)
#include <cuda_runtime.h>
#include <cuda_bf16.h>
#include <cstdint>

// Problem constants
#define NN   100000     // nodes
#define NE   1600000    // edges
#define FIN  128        // input features
#define HID  64         // hidden
#define NC   32         // classes

#define SCAN_BLK 512
#define NBS ((NN + SCAN_BLK - 1) / SCAN_BLK)   // 196

// ---------------- device scratch (static allocation only) ----------------
__device__ int   g_cnt [NN];        // in-degree (excl. self-loop)
__device__ int   g_off [NN];        // CSR offsets (exclusive prefix of cnt)
__device__ int   g_cur [NN];        // fill cursors
__device__ int   g_csr [NE];        // src ids grouped by dst
__device__ int   g_bsum[NBS];       // scan block sums
__device__ float g_dinv[NN];
__device__ float g_hs  [NN * HID];  // raw X@W (unscaled)
__device__ float g_h   [NN * HID];  // relu'd layer-1 output

// ---------------- degree counting / dinv ----------------
__global__ void k_zero_cnt() {
    int i = blockIdx.x * blockDim.x + threadIdx.x;
    if (i < NN) g_cnt[i] = 0;
}

__global__ void k_count(const int* __restrict__ dst) {
    int e = blockIdx.x * blockDim.x + threadIdx.x;
    if (e < NE) atomicAdd(&g_cnt[dst[e]], 1);
}

__global__ void k_dinv() {
    int i = blockIdx.x * blockDim.x + threadIdx.x;
    if (i < NN) g_dinv[i] = rsqrtf((float)g_cnt[i] + 1.0f);   // + self-loop
}

// ---------------- CSR build: 3-step scan + bucket fill ----------------
__global__ void k_scan_blocksum() {
    __shared__ int sm[SCAN_BLK];
    int t = threadIdx.x;
    int i = blockIdx.x * SCAN_BLK + t;
    sm[t] = (i < NN) ? g_cnt[i] : 0;
    __syncthreads();
#pragma unroll
    for (int s = SCAN_BLK / 2; s > 0; s >>= 1) {
        if (t < s) sm[t] += sm[t + s];
        __syncthreads();
    }
    if (t == 0) g_bsum[blockIdx.x] = sm[0];
}

__global__ void k_scan_bsum() {     // single block of 256, NBS=196 <= 256
    __shared__ int sm[256];
    int t = threadIdx.x;
    int orig = (t < NBS) ? g_bsum[t] : 0;
    sm[t] = orig;
    __syncthreads();
#pragma unroll
    for (int d = 1; d < 256; d <<= 1) {
        int v = (t >= d) ? sm[t - d] : 0;
        __syncthreads();
        sm[t] += v;
        __syncthreads();
    }
    if (t < NBS) g_bsum[t] = sm[t] - orig;   // exclusive
}

__global__ void k_scan_write() {
    __shared__ int sm[SCAN_BLK];
    int t = threadIdx.x;
    int i = blockIdx.x * SCAN_BLK + t;
    int v = (i < NN) ? g_cnt[i] : 0;
    sm[t] = v;
    __syncthreads();
#pragma unroll
    for (int d = 1; d < SCAN_BLK; d <<= 1) {
        int u = (t >= d) ? sm[t - d] : 0;
        __syncthreads();
        sm[t] += u;
        __syncthreads();
    }
    if (i < NN) {
        int off = g_bsum[blockIdx.x] + sm[t] - v;   // exclusive prefix
        g_off[i] = off;
        g_cur[i] = off;
    }
}

__global__ void k_fill(const int* __restrict__ src, const int* __restrict__ dst) {
    int e = blockIdx.x * blockDim.x + threadIdx.x;
    if (e < NE) {
        int d = dst[e];
        int pos = atomicAdd(&g_cur[d], 1);
        g_csr[pos] = src[e];
    }
}

// ---------------- register-tiled GEMM (raw, no dinv scaling):
// hs[row][col] = sum_k X[row][k] * W[k][col]
// Block: 256 threads, tile 128 rows x 64 cols, K-tiles of 32.
template<int K, bool FROM_GH>
__global__ __launch_bounds__(256) void k_gemm(const float* __restrict__ X,
                                              const float* __restrict__ W)
{
    __shared__ float Xs[128 * 32];   // [row][kk] 16KB
    __shared__ float Ws[32 * 64];    // [kk][col]  8KB

    const float* Xp = FROM_GH ? g_h : X;
    const int tid  = threadIdx.x;
    const int row0 = blockIdx.x * 128;
    const int tx = tid & 15;         // cols tx*4 .. tx*4+3
    const int ty = tid >> 4;         // rows ty*8 .. ty*8+7

    float acc[8][4];
#pragma unroll
    for (int j = 0; j < 8; j++)
#pragma unroll
        for (int c = 0; c < 4; c++) acc[j][c] = 0.0f;

    for (int kt = 0; kt < K; kt += 32) {
#pragma unroll
        for (int i = tid; i < 1024; i += 256) {
            int r = i >> 3, f = i & 7;
            int row = row0 + r;
            float4 v = make_float4(0.f, 0.f, 0.f, 0.f);
            if (row < NN)
                v = *reinterpret_cast<const float4*>(&Xp[(size_t)row * K + kt + f * 4]);
            *reinterpret_cast<float4*>(&Xs[r * 32 + f * 4]) = v;
        }
#pragma unroll
        for (int i = tid; i < 512; i += 256) {
            int kk = i >> 4, f = i & 15;
            *reinterpret_cast<float4*>(&Ws[kk * 64 + f * 4]) =
                *reinterpret_cast<const float4*>(&W[(size_t)(kt + kk) * 64 + f * 4]);
        }
        __syncthreads();

#pragma unroll
        for (int kk = 0; kk < 32; kk++) {
            float4 wv = *reinterpret_cast<const float4*>(&Ws[kk * 64 + tx * 4]);
#pragma unroll
            for (int j = 0; j < 8; j++) {
                float xv = Xs[(ty * 8 + j) * 32 + kk];   // warp-broadcast
                acc[j][0] = fmaf(xv, wv.x, acc[j][0]);
                acc[j][1] = fmaf(xv, wv.y, acc[j][1]);
                acc[j][2] = fmaf(xv, wv.z, acc[j][2]);
                acc[j][3] = fmaf(xv, wv.w, acc[j][3]);
            }
        }
        __syncthreads();
    }

#pragma unroll
    for (int j = 0; j < 8; j++) {
        int row = row0 + ty * 8 + j;
        if (row < NN) {
            float4 o = make_float4(acc[j][0], acc[j][1], acc[j][2], acc[j][3]);
            *reinterpret_cast<float4*>(&g_hs[(size_t)row * HID + tx * 4]) = o;
        }
    }
}

// ---------------- gather-aggregate-finalize (+ optional fused softmax head)
// h[i] = relu(dinv[i] * (sum_e dinv[src_e]*hs[src_e] + dinv[i]*hs[i]) + b)
// One warp per node. half = lane>>4 selects edge slot, c4 = lane&15 selects
// a float4 feature chunk. If FUSE: compute softmax(h @ Wout + bout) -> out.
template<bool FUSE>
__global__ __launch_bounds__(256) void k_gather_fin(const float* __restrict__ b,
                                                    const float* __restrict__ Wout,
                                                    const float* __restrict__ bout,
                                                    float* __restrict__ out)
{
    __shared__ float Wsm [FUSE ? HID * NC : 1];   // 8KB when fused
    __shared__ float Hrow[FUSE ? 8 * HID : 1];    // 2KB when fused

    const int tid  = threadIdx.x;
    const int wid  = tid >> 5;
    const int lane = tid & 31;

    float bo = 0.f;
    if (FUSE) {
        for (int i = tid; i < HID * NC; i += 256) Wsm[i] = Wout[i];
        bo = __ldg(&bout[lane]);
        __syncthreads();
    }

    int w = blockIdx.x * 8 + wid;
    if (w >= NN) return;
    const int half = lane >> 4;          // 0 or 1: which edge of the pair
    const int c4   = lane & 15;          // float4 chunk index

    const int off = __ldg(&g_off[w]);
    const int cnt = __ldg(&g_cnt[w]);

    float4 acc  = make_float4(0.f, 0.f, 0.f, 0.f);
    float4 acc2 = make_float4(0.f, 0.f, 0.f, 0.f);

    int j = 0;
    for (; j + 4 <= cnt; j += 4) {
        int s0 = __ldg(&g_csr[off + j + half]);        // broadcast within half
        int s1 = __ldg(&g_csr[off + j + 2 + half]);
        float ds0 = __ldg(&g_dinv[s0]);
        float ds1 = __ldg(&g_dinv[s1]);
        float4 v0 = *reinterpret_cast<const float4*>(&g_hs[(size_t)s0 * HID + c4 * 4]);
        float4 v1 = *reinterpret_cast<const float4*>(&g_hs[(size_t)s1 * HID + c4 * 4]);
        acc.x  = fmaf(v0.x, ds0, acc.x);  acc.y  = fmaf(v0.y, ds0, acc.y);
        acc.z  = fmaf(v0.z, ds0, acc.z);  acc.w  = fmaf(v0.w, ds0, acc.w);
        acc2.x = fmaf(v1.x, ds1, acc2.x); acc2.y = fmaf(v1.y, ds1, acc2.y);
        acc2.z = fmaf(v1.z, ds1, acc2.z); acc2.w = fmaf(v1.w, ds1, acc2.w);
    }
    for (; j < cnt; j += 2) {                          // tail: up to 3 edges
        if (j + half < cnt) {
            int s = __ldg(&g_csr[off + j + half]);
            float ds = __ldg(&g_dinv[s]);
            float4 v = *reinterpret_cast<const float4*>(&g_hs[(size_t)s * HID + c4 * 4]);
            acc.x = fmaf(v.x, ds, acc.x); acc.y = fmaf(v.y, ds, acc.y);
            acc.z = fmaf(v.z, ds, acc.z); acc.w = fmaf(v.w, ds, acc.w);
        }
    }
    acc.x += acc2.x; acc.y += acc2.y; acc.z += acc2.z; acc.w += acc2.w;

    // cross-half reduction: lane l += lane l^16
    acc.x += __shfl_xor_sync(0xffffffffu, acc.x, 16);
    acc.y += __shfl_xor_sync(0xffffffffu, acc.y, 16);
    acc.z += __shfl_xor_sync(0xffffffffu, acc.z, 16);
    acc.w += __shfl_xor_sync(0xffffffffu, acc.w, 16);

    const float dv = __ldg(&g_dinv[w]);

    if (half == 0) {
        float4 hv = *reinterpret_cast<const float4*>(&g_hs[(size_t)w * HID + c4 * 4]);
        float4 bb = *reinterpret_cast<const float4*>(&b[c4 * 4]);
        float4 o;
        o.x = fmaxf(fmaf(dv, fmaf(dv, hv.x, acc.x), bb.x), 0.f);
        o.y = fmaxf(fmaf(dv, fmaf(dv, hv.y, acc.y), bb.y), 0.f);
        o.z = fmaxf(fmaf(dv, fmaf(dv, hv.z, acc.z), bb.z), 0.f);
        o.w = fmaxf(fmaf(dv, fmaf(dv, hv.w, acc.w), bb.w), 0.f);
        if (FUSE)
            *reinterpret_cast<float4*>(&Hrow[wid * HID + c4 * 4]) = o;
        else
            *reinterpret_cast<float4*>(&g_h[(size_t)w * HID + c4 * 4]) = o;
    }

    if (FUSE) {
        __syncwarp();
        // logits: each lane = one class
        float lg = bo;
#pragma unroll
        for (int k = 0; k < HID; k++)
            lg = fmaf(Hrow[wid * HID + k], Wsm[k * NC + lane], lg);

        // stable softmax over 32 lanes
        float m = lg;
#pragma unroll
        for (int o2 = 16; o2; o2 >>= 1)
            m = fmaxf(m, __shfl_xor_sync(0xffffffffu, m, o2));
        float ex = __expf(lg - m);
        float s = ex;
#pragma unroll
        for (int o2 = 16; o2; o2 >>= 1)
            s += __shfl_xor_sync(0xffffffffu, s, o2);

        out[(size_t)w * NC + lane] = ex / s;
    }
}

// ---------------- stream/event handles (created once; no device mem) -----
struct ForkHandles {
    cudaStream_t s2;
    cudaEvent_t  eFork, eJoin;
    ForkHandles() {
        cudaStreamCreateWithFlags(&s2, cudaStreamNonBlocking);
        cudaEventCreateWithFlags(&eFork, cudaEventDisableTiming);
        cudaEventCreateWithFlags(&eJoin, cudaEventDisableTiming);
    }
};

// ---------------- launcher ----------------
extern "C" void kernel_launch(void* const* d_in, const int* in_sizes, int n_in,
                              void* d_out, int out_size)
{
    static ForkHandles fh;   // same capture structure on every call

    const float* x    = (const float*)d_in[0];
    const int*   ei   = (const int*)  d_in[1];   // [2, E]
    const float* W1   = (const float*)d_in[2];
    const float* b1   = (const float*)d_in[3];
    const float* W2   = (const float*)d_in[4];
    const float* b2   = (const float*)d_in[5];
    const float* Wout = (const float*)d_in[6];
    const float* bout = (const float*)d_in[7];
    float* out = (float*)d_out;

    const int* src = ei;
    const int* dst = ei + NE;

    const int TB = 256;
    int gN    = (NN + TB - 1) / TB;            // 391
    int gE    = (NE + TB - 1) / TB;            // 6250
    int gGemm = (NN + 127) / 128;              // 782
    int gGath = (NN + 7) / 8;                  // 12500 (one warp per node)

    // ---- fork at t=0: entire CSR/degree chain parallel to GEMM1 ----
    cudaEventRecord(fh.eFork, 0);
    cudaStreamWaitEvent(fh.s2, fh.eFork, 0);

    k_zero_cnt     <<<gN, TB,        0, fh.s2>>>();
    k_count        <<<gE, TB,        0, fh.s2>>>(dst);
    k_dinv         <<<gN, TB,        0, fh.s2>>>();
    k_scan_blocksum<<<NBS, SCAN_BLK, 0, fh.s2>>>();
    k_scan_bsum    <<<1, 256,        0, fh.s2>>>();
    k_scan_write   <<<NBS, SCAN_BLK, 0, fh.s2>>>();
    k_fill         <<<gE, TB,        0, fh.s2>>>(src, dst);
    cudaEventRecord(fh.eJoin, fh.s2);

    // main branch: layer-1 GEMM (raw, no dinv dependency)
    k_gemm<FIN, false><<<gGemm, TB>>>(x, W1);

    // ---- join: gather needs GEMM1 (g_hs) + CSR (g_off/g_csr/g_dinv) ----
    cudaStreamWaitEvent(0, fh.eJoin, 0);

    // layer 1 aggregation
    k_gather_fin<false><<<gGath, TB>>>(b1, nullptr, nullptr, nullptr);

    // layer 2 + fused softmax head
    k_gemm<HID, true><<<gGemm, TB>>>(nullptr, W2);
    k_gather_fin<true><<<gGath, TB>>>(b2, Wout, bout, out);
}

// round 10
// speedup vs baseline: 1.0012x; 1.0012x over previous
#include <cuda_runtime.h>
#include <cuda_bf16.h>
#include <cstdint>

// Problem constants
#define NN   100000     // nodes
#define NE   1600000    // edges
#define FIN  128        // input features
#define HID  64         // hidden
#define NC   32         // classes

#define SCAN_BLK 512
#define NBS ((NN + SCAN_BLK - 1) / SCAN_BLK)   // 196

// ---------------- device scratch (static allocation only) ----------------
__device__ int   g_cnt [NN];        // in-degree (excl. self-loop)
__device__ int   g_off [NN];        // CSR offsets (exclusive prefix of cnt)
__device__ int   g_cur [NN];        // fill cursors
__device__ int   g_csr [NE];        // src ids grouped by dst
__device__ int   g_bsum[NBS];       // scan block sums
__device__ float g_dinv[NN];
__device__ float g_hs  [NN * HID];  // dinv-scaled X@W
__device__ float g_h   [NN * HID];  // relu'd layer-1 output

// ---------------- degree counting / dinv ----------------
__global__ void k_zero_cnt() {
    int i = blockIdx.x * blockDim.x + threadIdx.x;
    if (i < NN) g_cnt[i] = 0;
}

__global__ void k_count(const int* __restrict__ dst) {
    int e = blockIdx.x * blockDim.x + threadIdx.x;
    if (e < NE) atomicAdd(&g_cnt[dst[e]], 1);
}

__global__ void k_dinv() {
    int i = blockIdx.x * blockDim.x + threadIdx.x;
    if (i < NN) g_dinv[i] = rsqrtf((float)g_cnt[i] + 1.0f);   // + self-loop
}

// ---------------- CSR build: 3-step scan + bucket fill ----------------
__global__ void k_scan_blocksum() {
    __shared__ int sm[SCAN_BLK];
    int t = threadIdx.x;
    int i = blockIdx.x * SCAN_BLK + t;
    sm[t] = (i < NN) ? g_cnt[i] : 0;
    __syncthreads();
#pragma unroll
    for (int s = SCAN_BLK / 2; s > 0; s >>= 1) {
        if (t < s) sm[t] += sm[t + s];
        __syncthreads();
    }
    if (t == 0) g_bsum[blockIdx.x] = sm[0];
}

__global__ void k_scan_bsum() {     // single block of 256, NBS=196 <= 256
    __shared__ int sm[256];
    int t = threadIdx.x;
    int orig = (t < NBS) ? g_bsum[t] : 0;
    sm[t] = orig;
    __syncthreads();
#pragma unroll
    for (int d = 1; d < 256; d <<= 1) {
        int v = (t >= d) ? sm[t - d] : 0;
        __syncthreads();
        sm[t] += v;
        __syncthreads();
    }
    if (t < NBS) g_bsum[t] = sm[t] - orig;   // exclusive
}

__global__ void k_scan_write() {
    __shared__ int sm[SCAN_BLK];
    int t = threadIdx.x;
    int i = blockIdx.x * SCAN_BLK + t;
    int v = (i < NN) ? g_cnt[i] : 0;
    sm[t] = v;
    __syncthreads();
#pragma unroll
    for (int d = 1; d < SCAN_BLK; d <<= 1) {
        int u = (t >= d) ? sm[t - d] : 0;
        __syncthreads();
        sm[t] += u;
        __syncthreads();
    }
    if (i < NN) {
        int off = g_bsum[blockIdx.x] + sm[t] - v;   // exclusive prefix
        g_off[i] = off;
        g_cur[i] = off;
    }
}

__global__ void k_fill(const int* __restrict__ src, const int* __restrict__ dst) {
    int e = blockIdx.x * blockDim.x + threadIdx.x;
    if (e < NE) {
        int d = dst[e];
        int pos = atomicAdd(&g_cur[d], 1);
        g_csr[pos] = src[e];
    }
}

// ---------------- post-GEMM1 scaling: hs[i] *= dinv[i] -------------------
__global__ void k_scale_hs() {
    int t = blockIdx.x * blockDim.x + threadIdx.x;   // NN*16 float4 chunks
    if (t >= NN * 16) return;
    int i = t >> 4, p = t & 15;
    float dv = g_dinv[i];
    float4 v = *reinterpret_cast<const float4*>(&g_hs[(size_t)i * HID + p * 4]);
    v.x *= dv; v.y *= dv; v.z *= dv; v.w *= dv;
    *reinterpret_cast<float4*>(&g_hs[(size_t)i * HID + p * 4]) = v;
}

// ---------------- register-tiled GEMM:
// hs[row][col] = (SCALE ? dinv[row] : 1) * sum_k X[row][k] * W[k][col]
// Block: 256 threads, tile 128 rows x 64 cols, K-tiles of 32.
template<int K, bool FROM_GH, bool SCALE>
__global__ __launch_bounds__(256) void k_gemm(const float* __restrict__ X,
                                              const float* __restrict__ W)
{
    __shared__ float Xs[128 * 32];   // [row][kk] 16KB
    __shared__ float Ws[32 * 64];    // [kk][col]  8KB

    const float* Xp = FROM_GH ? g_h : X;
    const int tid  = threadIdx.x;
    const int row0 = blockIdx.x * 128;
    const int tx = tid & 15;         // cols tx*4 .. tx*4+3
    const int ty = tid >> 4;         // rows ty*8 .. ty*8+7

    float acc[8][4];
#pragma unroll
    for (int j = 0; j < 8; j++)
#pragma unroll
        for (int c = 0; c < 4; c++) acc[j][c] = 0.0f;

    for (int kt = 0; kt < K; kt += 32) {
#pragma unroll
        for (int i = tid; i < 1024; i += 256) {
            int r = i >> 3, f = i & 7;
            int row = row0 + r;
            float4 v = make_float4(0.f, 0.f, 0.f, 0.f);
            if (row < NN)
                v = *reinterpret_cast<const float4*>(&Xp[(size_t)row * K + kt + f * 4]);
            *reinterpret_cast<float4*>(&Xs[r * 32 + f * 4]) = v;
        }
#pragma unroll
        for (int i = tid; i < 512; i += 256) {
            int kk = i >> 4, f = i & 15;
            *reinterpret_cast<float4*>(&Ws[kk * 64 + f * 4]) =
                *reinterpret_cast<const float4*>(&W[(size_t)(kt + kk) * 64 + f * 4]);
        }
        __syncthreads();

#pragma unroll
        for (int kk = 0; kk < 32; kk++) {
            float4 wv = *reinterpret_cast<const float4*>(&Ws[kk * 64 + tx * 4]);
#pragma unroll
            for (int j = 0; j < 8; j++) {
                float xv = Xs[(ty * 8 + j) * 32 + kk];   // warp-broadcast
                acc[j][0] = fmaf(xv, wv.x, acc[j][0]);
                acc[j][1] = fmaf(xv, wv.y, acc[j][1]);
                acc[j][2] = fmaf(xv, wv.z, acc[j][2]);
                acc[j][3] = fmaf(xv, wv.w, acc[j][3]);
            }
        }
        __syncthreads();
    }

#pragma unroll
    for (int j = 0; j < 8; j++) {
        int row = row0 + ty * 8 + j;
        if (row < NN) {
            float dv = SCALE ? g_dinv[row] : 1.0f;
            float4 o = make_float4(acc[j][0] * dv, acc[j][1] * dv,
                                   acc[j][2] * dv, acc[j][3] * dv);
            *reinterpret_cast<float4*>(&g_hs[(size_t)row * HID + tx * 4]) = o;
        }
    }
}

// ---------------- gather-aggregate-finalize (+ optional fused softmax head)
// hs is pre-scaled by dinv.  h[i] = relu(dinv[i]*(sum_e hs[src_e] + hs[i]) + b)
// One warp per node. half = lane>>4 selects edge slot, c4 = lane&15 selects
// a float4 feature chunk. If FUSE: compute softmax(h @ Wout + bout) -> out.
template<bool FUSE>
__global__ __launch_bounds__(256) void k_gather_fin(const float* __restrict__ b,
                                                    const float* __restrict__ Wout,
                                                    const float* __restrict__ bout,
                                                    float* __restrict__ out)
{
    __shared__ float Wsm [FUSE ? HID * NC : 1];   // 8KB when fused
    __shared__ float Hrow[FUSE ? 8 * HID : 1];    // 2KB when fused

    const int tid  = threadIdx.x;
    const int wid  = tid >> 5;
    const int lane = tid & 31;

    float bo = 0.f;
    if (FUSE) {
        for (int i = tid; i < HID * NC; i += 256) Wsm[i] = Wout[i];
        bo = __ldg(&bout[lane]);
        __syncthreads();
    }

    int w = blockIdx.x * 8 + wid;
    if (w >= NN) return;
    const int half = lane >> 4;          // 0 or 1: which edge of the pair
    const int c4   = lane & 15;          // float4 chunk index

    const int off = __ldg(&g_off[w]);
    const int cnt = __ldg(&g_cnt[w]);

    float4 acc  = make_float4(0.f, 0.f, 0.f, 0.f);
    float4 acc2 = make_float4(0.f, 0.f, 0.f, 0.f);

    int j = 0;
    for (; j + 4 <= cnt; j += 4) {
        int s0 = __ldg(&g_csr[off + j + half]);        // broadcast within half
        int s1 = __ldg(&g_csr[off + j + 2 + half]);
        float4 v0 = *reinterpret_cast<const float4*>(&g_hs[(size_t)s0 * HID + c4 * 4]);
        float4 v1 = *reinterpret_cast<const float4*>(&g_hs[(size_t)s1 * HID + c4 * 4]);
        acc.x  += v0.x; acc.y  += v0.y; acc.z  += v0.z; acc.w  += v0.w;
        acc2.x += v1.x; acc2.y += v1.y; acc2.z += v1.z; acc2.w += v1.w;
    }
    for (; j < cnt; j += 2) {                          // tail: up to 3 edges
        if (j + half < cnt) {
            int s = __ldg(&g_csr[off + j + half]);
            float4 v = *reinterpret_cast<const float4*>(&g_hs[(size_t)s * HID + c4 * 4]);
            acc.x += v.x; acc.y += v.y; acc.z += v.z; acc.w += v.w;
        }
    }
    acc.x += acc2.x; acc.y += acc2.y; acc.z += acc2.z; acc.w += acc2.w;

    // cross-half reduction: lane l += lane l^16
    acc.x += __shfl_xor_sync(0xffffffffu, acc.x, 16);
    acc.y += __shfl_xor_sync(0xffffffffu, acc.y, 16);
    acc.z += __shfl_xor_sync(0xffffffffu, acc.z, 16);
    acc.w += __shfl_xor_sync(0xffffffffu, acc.w, 16);

    const float dv = __ldg(&g_dinv[w]);

    if (half == 0) {
        float4 hv = *reinterpret_cast<const float4*>(&g_hs[(size_t)w * HID + c4 * 4]);
        float4 bb = *reinterpret_cast<const float4*>(&b[c4 * 4]);
        float4 o;
        o.x = fmaxf(fmaf(dv, acc.x + hv.x, bb.x), 0.f);
        o.y = fmaxf(fmaf(dv, acc.y + hv.y, bb.y), 0.f);
        o.z = fmaxf(fmaf(dv, acc.z + hv.z, bb.z), 0.f);
        o.w = fmaxf(fmaf(dv, acc.w + hv.w, bb.w), 0.f);
        if (FUSE)
            *reinterpret_cast<float4*>(&Hrow[wid * HID + c4 * 4]) = o;
        else
            *reinterpret_cast<float4*>(&g_h[(size_t)w * HID + c4 * 4]) = o;
    }

    if (FUSE) {
        __syncwarp();
        // logits: each lane = one class
        float lg = bo;
#pragma unroll
        for (int k = 0; k < HID; k++)
            lg = fmaf(Hrow[wid * HID + k], Wsm[k * NC + lane], lg);

        // stable softmax over 32 lanes
        float m = lg;
#pragma unroll
        for (int o2 = 16; o2; o2 >>= 1)
            m = fmaxf(m, __shfl_xor_sync(0xffffffffu, m, o2));
        float ex = __expf(lg - m);
        float s = ex;
#pragma unroll
        for (int o2 = 16; o2; o2 >>= 1)
            s += __shfl_xor_sync(0xffffffffu, s, o2);

        out[(size_t)w * NC + lane] = ex / s;
    }
}

// ---------------- stream/event handles (created once; no device mem) -----
struct ForkHandles {
    cudaStream_t s2;
    cudaEvent_t  eFork, eJoin;
    ForkHandles() {
        cudaStreamCreateWithFlags(&s2, cudaStreamNonBlocking);
        cudaEventCreateWithFlags(&eFork, cudaEventDisableTiming);
        cudaEventCreateWithFlags(&eJoin, cudaEventDisableTiming);
    }
};

// ---------------- launcher ----------------
extern "C" void kernel_launch(void* const* d_in, const int* in_sizes, int n_in,
                              void* d_out, int out_size)
{
    static ForkHandles fh;   // same capture structure on every call

    const float* x    = (const float*)d_in[0];
    const int*   ei   = (const int*)  d_in[1];   // [2, E]
    const float* W1   = (const float*)d_in[2];
    const float* b1   = (const float*)d_in[3];
    const float* W2   = (const float*)d_in[4];
    const float* b2   = (const float*)d_in[5];
    const float* Wout = (const float*)d_in[6];
    const float* bout = (const float*)d_in[7];
    float* out = (float*)d_out;

    const int* src = ei;
    const int* dst = ei + NE;

    const int TB = 256;
    int gN    = (NN + TB - 1) / TB;            // 391
    int gE    = (NE + TB - 1) / TB;            // 6250
    int gGemm = (NN + 127) / 128;              // 782
    int gGath = (NN + 7) / 8;                  // 12500 (one warp per node)
    int gScl  = (NN * 16 + TB - 1) / TB;       // 6250

    // ---- fork at t=0: entire CSR/degree chain parallel to raw GEMM1 ----
    cudaEventRecord(fh.eFork, 0);
    cudaStreamWaitEvent(fh.s2, fh.eFork, 0);

    k_zero_cnt     <<<gN, TB,        0, fh.s2>>>();
    k_count        <<<gE, TB,        0, fh.s2>>>(dst);
    k_dinv         <<<gN, TB,        0, fh.s2>>>();
    k_scan_blocksum<<<NBS, SCAN_BLK, 0, fh.s2>>>();
    k_scan_bsum    <<<1, 256,        0, fh.s2>>>();
    k_scan_write   <<<NBS, SCAN_BLK, 0, fh.s2>>>();
    k_fill         <<<gE, TB,        0, fh.s2>>>(src, dst);
    cudaEventRecord(fh.eJoin, fh.s2);

    // main branch: layer-1 GEMM, raw (no dinv dependency)
    k_gemm<FIN, false, false><<<gGemm, TB>>>(x, W1);

    // ---- join, then scale hs by dinv (cheap, 51MB L2 traffic) ----
    cudaStreamWaitEvent(0, fh.eJoin, 0);
    k_scale_hs<<<gScl, TB>>>();

    // layer 1 aggregation
    k_gather_fin<false><<<gGath, TB>>>(b1, nullptr, nullptr, nullptr);

    // layer 2 (dinv folded into epilogue) + fused softmax head
    k_gemm<HID, true, true><<<gGemm, TB>>>(nullptr, W2);
    k_gather_fin<true><<<gGath, TB>>>(b2, Wout, bout, out);
}

// round 11
// speedup vs baseline: 1.0727x; 1.0714x over previous
#include <cuda_runtime.h>
#include <cuda_fp16.h>
#include <cuda_bf16.h>
#include <cstdint>

// Problem constants
#define NN   100000     // nodes
#define NE   1600000    // edges
#define FIN  128        // input features
#define HID  64         // hidden
#define NC   32         // classes

#define SCAN_BLK 512
#define NBS ((NN + SCAN_BLK - 1) / SCAN_BLK)   // 196

// ---------------- device scratch (static allocation only) ----------------
__device__ int    g_cnt [NN];        // in-degree (excl. self-loop)
__device__ int    g_off [NN];        // CSR offsets (exclusive prefix of cnt)
__device__ int    g_cur [NN];        // fill cursors
__device__ int    g_csr [NE];        // src ids grouped by dst
__device__ int    g_bsum[NBS];       // scan block sums
__device__ float  g_dinv[NN];
__device__ __half g_hs16[NN * HID];  // layer-1: dinv-scaled X@W1 (fp16)
__device__ float  g_hs  [NN * HID];  // layer-2: dinv-scaled H@W2 (fp32)
__device__ float  g_h   [NN * HID];  // relu'd layer-1 output

// ---------------- degree counting / dinv ----------------
__global__ void k_count(const int* __restrict__ dst) {
    int e = blockIdx.x * blockDim.x + threadIdx.x;
    if (e < NE) atomicAdd(&g_cnt[dst[e]], 1);
}

__global__ void k_dinv() {
    int i = blockIdx.x * blockDim.x + threadIdx.x;
    if (i < NN) g_dinv[i] = rsqrtf((float)g_cnt[i] + 1.0f);   // + self-loop
}

// ---------------- CSR build: 3-step scan + bucket fill ----------------
__global__ void k_scan_blocksum() {
    __shared__ int sm[SCAN_BLK];
    int t = threadIdx.x;
    int i = blockIdx.x * SCAN_BLK + t;
    sm[t] = (i < NN) ? g_cnt[i] : 0;
    __syncthreads();
#pragma unroll
    for (int s = SCAN_BLK / 2; s > 0; s >>= 1) {
        if (t < s) sm[t] += sm[t + s];
        __syncthreads();
    }
    if (t == 0) g_bsum[blockIdx.x] = sm[0];
}

__global__ void k_scan_bsum() {     // single block of 256, NBS=196 <= 256
    __shared__ int sm[256];
    int t = threadIdx.x;
    int orig = (t < NBS) ? g_bsum[t] : 0;
    sm[t] = orig;
    __syncthreads();
#pragma unroll
    for (int d = 1; d < 256; d <<= 1) {
        int v = (t >= d) ? sm[t - d] : 0;
        __syncthreads();
        sm[t] += v;
        __syncthreads();
    }
    if (t < NBS) g_bsum[t] = sm[t] - orig;   // exclusive
}

__global__ void k_scan_write() {
    __shared__ int sm[SCAN_BLK];
    int t = threadIdx.x;
    int i = blockIdx.x * SCAN_BLK + t;
    int v = (i < NN) ? g_cnt[i] : 0;
    sm[t] = v;
    __syncthreads();
#pragma unroll
    for (int d = 1; d < SCAN_BLK; d <<= 1) {
        int u = (t >= d) ? sm[t - d] : 0;
        __syncthreads();
        sm[t] += u;
        __syncthreads();
    }
    if (i < NN) {
        int off = g_bsum[blockIdx.x] + sm[t] - v;   // exclusive prefix
        g_off[i] = off;
        g_cur[i] = off;
    }
}

__global__ void k_fill(const int* __restrict__ src, const int* __restrict__ dst) {
    int e = blockIdx.x * blockDim.x + threadIdx.x;
    if (e < NE) {
        int d = dst[e];
        int pos = atomicAdd(&g_cur[d], 1);
        g_csr[pos] = src[e];
    }
}

// ---------------- register-tiled GEMM:
// out[row][col] = dinv[row] * sum_k X[row][k] * W[k][col]
// OUT16: write fp16 to g_hs16 (layer 1).  else: fp32 to g_hs (layer 2).
template<int K, bool FROM_GH, bool OUT16>
__global__ __launch_bounds__(256) void k_gemm(const float* __restrict__ X,
                                              const float* __restrict__ W)
{
    __shared__ float Xs[128 * 32];   // [row][kk] 16KB
    __shared__ float Ws[32 * 64];    // [kk][col]  8KB

    const float* Xp = FROM_GH ? g_h : X;
    const int tid  = threadIdx.x;
    const int row0 = blockIdx.x * 128;
    const int tx = tid & 15;         // cols tx*4 .. tx*4+3
    const int ty = tid >> 4;         // rows ty*8 .. ty*8+7

    float acc[8][4];
#pragma unroll
    for (int j = 0; j < 8; j++)
#pragma unroll
        for (int c = 0; c < 4; c++) acc[j][c] = 0.0f;

    for (int kt = 0; kt < K; kt += 32) {
#pragma unroll
        for (int i = tid; i < 1024; i += 256) {
            int r = i >> 3, f = i & 7;
            int row = row0 + r;
            float4 v = make_float4(0.f, 0.f, 0.f, 0.f);
            if (row < NN)
                v = *reinterpret_cast<const float4*>(&Xp[(size_t)row * K + kt + f * 4]);
            *reinterpret_cast<float4*>(&Xs[r * 32 + f * 4]) = v;
        }
#pragma unroll
        for (int i = tid; i < 512; i += 256) {
            int kk = i >> 4, f = i & 15;
            *reinterpret_cast<float4*>(&Ws[kk * 64 + f * 4]) =
                *reinterpret_cast<const float4*>(&W[(size_t)(kt + kk) * 64 + f * 4]);
        }
        __syncthreads();

#pragma unroll
        for (int kk = 0; kk < 32; kk++) {
            float4 wv = *reinterpret_cast<const float4*>(&Ws[kk * 64 + tx * 4]);
#pragma unroll
            for (int j = 0; j < 8; j++) {
                float xv = Xs[(ty * 8 + j) * 32 + kk];   // warp-broadcast
                acc[j][0] = fmaf(xv, wv.x, acc[j][0]);
                acc[j][1] = fmaf(xv, wv.y, acc[j][1]);
                acc[j][2] = fmaf(xv, wv.z, acc[j][2]);
                acc[j][3] = fmaf(xv, wv.w, acc[j][3]);
            }
        }
        __syncthreads();
    }

#pragma unroll
    for (int j = 0; j < 8; j++) {
        int row = row0 + ty * 8 + j;
        if (row < NN) {
            float dv = g_dinv[row];
            float4 o = make_float4(acc[j][0] * dv, acc[j][1] * dv,
                                   acc[j][2] * dv, acc[j][3] * dv);
            if (OUT16) {
                __half2 p0 = __floats2half2_rn(o.x, o.y);
                __half2 p1 = __floats2half2_rn(o.z, o.w);
                uint2 pk;
                pk.x = *reinterpret_cast<unsigned*>(&p0);
                pk.y = *reinterpret_cast<unsigned*>(&p1);
                *reinterpret_cast<uint2*>(&g_hs16[(size_t)row * HID + tx * 4]) = pk;
            } else {
                *reinterpret_cast<float4*>(&g_hs[(size_t)row * HID + tx * 4]) = o;
            }
        }
    }
}

// ---------------- layer-1 gather (fp16 hs): one warp per node.
// q = lane>>3 selects edge-of-quad, c8 = lane&7 selects 8-feature chunk.
// h[i] = relu(dinv[i]*(sum_e hs[src_e] + hs[i]) + b)   (hs pre-scaled)
__global__ __launch_bounds__(256) void k_gather1(const float* __restrict__ b)
{
    int w = blockIdx.x * 8 + (threadIdx.x >> 5);
    if (w >= NN) return;
    const int lane = threadIdx.x & 31;
    const int q  = lane >> 3;        // 0..3: edge slot within quad
    const int c8 = lane & 7;         // 8-half chunk index

    const int off = __ldg(&g_off[w]);
    const int cnt = __ldg(&g_cnt[w]);

    float a0 = 0.f, a1 = 0.f, a2 = 0.f, a3 = 0.f;
    float a4 = 0.f, a5 = 0.f, a6 = 0.f, a7 = 0.f;

    int j = 0;
    for (; j + 4 <= cnt; j += 4) {
        int s = __ldg(&g_csr[off + j + q]);   // broadcast within 8-lane group
        uint4 v = *reinterpret_cast<const uint4*>(&g_hs16[(size_t)s * HID + c8 * 8]);
        const __half2* hp = reinterpret_cast<const __half2*>(&v);
        float2 f0 = __half22float2(hp[0]);
        float2 f1 = __half22float2(hp[1]);
        float2 f2 = __half22float2(hp[2]);
        float2 f3 = __half22float2(hp[3]);
        a0 += f0.x; a1 += f0.y; a2 += f1.x; a3 += f1.y;
        a4 += f2.x; a5 += f2.y; a6 += f3.x; a7 += f3.y;
    }
    if (j + q < cnt) {                        // tail: remaining 0..3 edges
        int s = __ldg(&g_csr[off + j + q]);
        uint4 v = *reinterpret_cast<const uint4*>(&g_hs16[(size_t)s * HID + c8 * 8]);
        const __half2* hp = reinterpret_cast<const __half2*>(&v);
        float2 f0 = __half22float2(hp[0]);
        float2 f1 = __half22float2(hp[1]);
        float2 f2 = __half22float2(hp[2]);
        float2 f3 = __half22float2(hp[3]);
        a0 += f0.x; a1 += f0.y; a2 += f1.x; a3 += f1.y;
        a4 += f2.x; a5 += f2.y; a6 += f3.x; a7 += f3.y;
    }

    // reduce across the 4 q-groups (lanes differing in bits 3,4)
#pragma unroll
    for (int d = 8; d <= 16; d <<= 1) {
        a0 += __shfl_xor_sync(0xffffffffu, a0, d);
        a1 += __shfl_xor_sync(0xffffffffu, a1, d);
        a2 += __shfl_xor_sync(0xffffffffu, a2, d);
        a3 += __shfl_xor_sync(0xffffffffu, a3, d);
        a4 += __shfl_xor_sync(0xffffffffu, a4, d);
        a5 += __shfl_xor_sync(0xffffffffu, a5, d);
        a6 += __shfl_xor_sync(0xffffffffu, a6, d);
        a7 += __shfl_xor_sync(0xffffffffu, a7, d);
    }

    if (q == 0) {
        // self-loop term (also fp16-stored, pre-scaled)
        uint4 v = *reinterpret_cast<const uint4*>(&g_hs16[(size_t)w * HID + c8 * 8]);
        const __half2* hp = reinterpret_cast<const __half2*>(&v);
        float2 f0 = __half22float2(hp[0]);
        float2 f1 = __half22float2(hp[1]);
        float2 f2 = __half22float2(hp[2]);
        float2 f3 = __half22float2(hp[3]);
        float dv  = __ldg(&g_dinv[w]);
        float4 b0 = *reinterpret_cast<const float4*>(&b[c8 * 8]);
        float4 b1 = *reinterpret_cast<const float4*>(&b[c8 * 8 + 4]);

        float4 o0, o1;
        o0.x = fmaxf(fmaf(dv, a0 + f0.x, b0.x), 0.f);
        o0.y = fmaxf(fmaf(dv, a1 + f0.y, b0.y), 0.f);
        o0.z = fmaxf(fmaf(dv, a2 + f1.x, b0.z), 0.f);
        o0.w = fmaxf(fmaf(dv, a3 + f1.y, b0.w), 0.f);
        o1.x = fmaxf(fmaf(dv, a4 + f2.x, b1.x), 0.f);
        o1.y = fmaxf(fmaf(dv, a5 + f2.y, b1.y), 0.f);
        o1.z = fmaxf(fmaf(dv, a6 + f3.x, b1.z), 0.f);
        o1.w = fmaxf(fmaf(dv, a7 + f3.y, b1.w), 0.f);

        *reinterpret_cast<float4*>(&g_h[(size_t)w * HID + c8 * 8])     = o0;
        *reinterpret_cast<float4*>(&g_h[(size_t)w * HID + c8 * 8 + 4]) = o1;
    }
}

// ---------------- layer-2 gather + fused softmax head (fp32 hs):
// 512 threads = 16 warps/block; one warp per node.
// half = lane>>4 selects edge pair slot, c4 = lane&15 selects float4 chunk.
__global__ __launch_bounds__(512) void k_gather2_head(const float* __restrict__ b,
                                                      const float* __restrict__ Wout,
                                                      const float* __restrict__ bout,
                                                      float* __restrict__ out)
{
    __shared__ float Wsm [HID * NC];   // 8KB
    __shared__ float Hrow[16 * HID];   // 4KB

    const int tid  = threadIdx.x;
    const int wid  = tid >> 5;
    const int lane = tid & 31;

    for (int i = tid; i < HID * NC; i += 512) Wsm[i] = Wout[i];
    float bo = __ldg(&bout[lane]);
    __syncthreads();

    int w = blockIdx.x * 16 + wid;
    if (w >= NN) return;               // whole warp exits together
    const int half = lane >> 4;
    const int c4   = lane & 15;

    const int off = __ldg(&g_off[w]);
    const int cnt = __ldg(&g_cnt[w]);

    float4 acc  = make_float4(0.f, 0.f, 0.f, 0.f);
    float4 acc2 = make_float4(0.f, 0.f, 0.f, 0.f);

    int j = 0;
    for (; j + 4 <= cnt; j += 4) {
        int s0 = __ldg(&g_csr[off + j + half]);
        int s1 = __ldg(&g_csr[off + j + 2 + half]);
        float4 v0 = *reinterpret_cast<const float4*>(&g_hs[(size_t)s0 * HID + c4 * 4]);
        float4 v1 = *reinterpret_cast<const float4*>(&g_hs[(size_t)s1 * HID + c4 * 4]);
        acc.x  += v0.x; acc.y  += v0.y; acc.z  += v0.z; acc.w  += v0.w;
        acc2.x += v1.x; acc2.y += v1.y; acc2.z += v1.z; acc2.w += v1.w;
    }
    for (; j < cnt; j += 2) {
        if (j + half < cnt) {
            int s = __ldg(&g_csr[off + j + half]);
            float4 v = *reinterpret_cast<const float4*>(&g_hs[(size_t)s * HID + c4 * 4]);
            acc.x += v.x; acc.y += v.y; acc.z += v.z; acc.w += v.w;
        }
    }
    acc.x += acc2.x; acc.y += acc2.y; acc.z += acc2.z; acc.w += acc2.w;

    acc.x += __shfl_xor_sync(0xffffffffu, acc.x, 16);
    acc.y += __shfl_xor_sync(0xffffffffu, acc.y, 16);
    acc.z += __shfl_xor_sync(0xffffffffu, acc.z, 16);
    acc.w += __shfl_xor_sync(0xffffffffu, acc.w, 16);

    const float dv = __ldg(&g_dinv[w]);

    if (half == 0) {
        float4 hv = *reinterpret_cast<const float4*>(&g_hs[(size_t)w * HID + c4 * 4]);
        float4 bb = *reinterpret_cast<const float4*>(&b[c4 * 4]);
        float4 o;
        o.x = fmaxf(fmaf(dv, acc.x + hv.x, bb.x), 0.f);
        o.y = fmaxf(fmaf(dv, acc.y + hv.y, bb.y), 0.f);
        o.z = fmaxf(fmaf(dv, acc.z + hv.z, bb.z), 0.f);
        o.w = fmaxf(fmaf(dv, acc.w + hv.w, bb.w), 0.f);
        *reinterpret_cast<float4*>(&Hrow[wid * HID + c4 * 4]) = o;
    }
    __syncwarp();

    // logits: each lane = one class; Wsm read is conflict-free, Hrow broadcast
    float lg = bo;
#pragma unroll
    for (int k = 0; k < HID; k++)
        lg = fmaf(Hrow[wid * HID + k], Wsm[k * NC + lane], lg);

    // stable softmax over 32 lanes
    float m = lg;
#pragma unroll
    for (int o2 = 16; o2; o2 >>= 1)
        m = fmaxf(m, __shfl_xor_sync(0xffffffffu, m, o2));
    float ex = __expf(lg - m);
    float s = ex;
#pragma unroll
    for (int o2 = 16; o2; o2 >>= 1)
        s += __shfl_xor_sync(0xffffffffu, s, o2);

    out[(size_t)w * NC + lane] = ex / s;
}

// ---------------- stream/event handles (created once; no device mem) -----
struct ForkHandles {
    cudaStream_t s2;
    cudaEvent_t  eFork, eJoin;
    void* cntPtr;
    ForkHandles() {
        cudaStreamCreateWithFlags(&s2, cudaStreamNonBlocking);
        cudaEventCreateWithFlags(&eFork, cudaEventDisableTiming);
        cudaEventCreateWithFlags(&eJoin, cudaEventDisableTiming);
        cudaGetSymbolAddress(&cntPtr, g_cnt);
    }
};

// ---------------- launcher ----------------
extern "C" void kernel_launch(void* const* d_in, const int* in_sizes, int n_in,
                              void* d_out, int out_size)
{
    static ForkHandles fh;   // same capture structure on every call

    const float* x    = (const float*)d_in[0];
    const int*   ei   = (const int*)  d_in[1];   // [2, E]
    const float* W1   = (const float*)d_in[2];
    const float* b1   = (const float*)d_in[3];
    const float* W2   = (const float*)d_in[4];
    const float* b2   = (const float*)d_in[5];
    const float* Wout = (const float*)d_in[6];
    const float* bout = (const float*)d_in[7];
    float* out = (float*)d_out;

    const int* src = ei;
    const int* dst = ei + NE;

    const int TB = 256;
    int gN    = (NN + TB - 1) / TB;            // 391
    int gE    = (NE + TB - 1) / TB;            // 6250
    int gGemm = (NN + 127) / 128;              // 782
    int gG1   = (NN + 7) / 8;                  // 12500
    int gG2   = (NN + 15) / 16;                // 6250

    // ---- counts (needed by dinv and the CSR chain) ----
    cudaMemsetAsync(fh.cntPtr, 0, NN * sizeof(int), 0);
    k_count<<<gE, TB>>>(dst);

    // ---- fork: scan/fill chain runs parallel to dinv + GEMM1 ----
    cudaEventRecord(fh.eFork, 0);
    cudaStreamWaitEvent(fh.s2, fh.eFork, 0);

    k_scan_blocksum<<<NBS, SCAN_BLK, 0, fh.s2>>>();
    k_scan_bsum    <<<1, 256,        0, fh.s2>>>();
    k_scan_write   <<<NBS, SCAN_BLK, 0, fh.s2>>>();
    k_fill         <<<gE, TB,        0, fh.s2>>>(src, dst);
    cudaEventRecord(fh.eJoin, fh.s2);

    // main branch: dinv + layer-1 GEMM (writes fp16 hs, dinv-scaled)
    k_dinv<<<gN, TB>>>();
    k_gemm<FIN, false, true><<<gGemm, TB>>>(x, W1);

    // ---- join: gather needs GEMM1 (g_hs16) + CSR (g_off/g_csr) ----
    cudaStreamWaitEvent(0, fh.eJoin, 0);

    // layer 1 aggregation (fp16 gather, fp32 accumulate)
    k_gather1<<<gG1, TB>>>(b1);

    // layer 2 (fp32) + fused softmax head
    k_gemm<HID, true, false><<<gGemm, TB>>>(nullptr, W2);
    k_gather2_head<<<gG2, 512>>>(b2, Wout, bout, out);
}

// round 12
// speedup vs baseline: 1.0929x; 1.0188x over previous
#include <cuda_runtime.h>
#include <cuda_fp16.h>
#include <cuda_bf16.h>
#include <cstdint>

// Problem constants
#define NN   100000     // nodes
#define NE   1600000    // edges
#define FIN  128        // input features
#define HID  64         // hidden
#define NC   32         // classes

#define SCAN_BLK 512
#define NBS ((NN + SCAN_BLK - 1) / SCAN_BLK)   // 196

// ---------------- device scratch (static allocation only) ----------------
__device__ int    g_cnt [NN];        // in-degree (excl. self-loop)
__device__ int    g_off [NN];        // CSR offsets (exclusive prefix of cnt)
__device__ int    g_cur [NN];        // fill cursors
__device__ int    g_csr [NE];        // src ids grouped by dst
__device__ int    g_bsum[NBS];       // scan block sums
__device__ float  g_dinv[NN];
__device__ __half g_hs16[NN * HID];  // dinv-scaled X@W (fp16, reused both layers)
__device__ float  g_h   [NN * HID];  // relu'd layer-1 output

// ---------------- degree counting / dinv ----------------
__global__ void k_count(const int* __restrict__ dst) {
    int e = blockIdx.x * blockDim.x + threadIdx.x;
    if (e < NE) atomicAdd(&g_cnt[dst[e]], 1);
}

__global__ void k_dinv() {
    int i = blockIdx.x * blockDim.x + threadIdx.x;
    if (i < NN) g_dinv[i] = rsqrtf((float)g_cnt[i] + 1.0f);   // + self-loop
}

// ---------------- CSR build: 3-step scan + bucket fill ----------------
__global__ void k_scan_blocksum() {
    __shared__ int sm[SCAN_BLK];
    int t = threadIdx.x;
    int i = blockIdx.x * SCAN_BLK + t;
    sm[t] = (i < NN) ? g_cnt[i] : 0;
    __syncthreads();
#pragma unroll
    for (int s = SCAN_BLK / 2; s > 0; s >>= 1) {
        if (t < s) sm[t] += sm[t + s];
        __syncthreads();
    }
    if (t == 0) g_bsum[blockIdx.x] = sm[0];
}

__global__ void k_scan_bsum() {     // single block of 256, NBS=196 <= 256
    __shared__ int sm[256];
    int t = threadIdx.x;
    int orig = (t < NBS) ? g_bsum[t] : 0;
    sm[t] = orig;
    __syncthreads();
#pragma unroll
    for (int d = 1; d < 256; d <<= 1) {
        int v = (t >= d) ? sm[t - d] : 0;
        __syncthreads();
        sm[t] += v;
        __syncthreads();
    }
    if (t < NBS) g_bsum[t] = sm[t] - orig;   // exclusive
}

__global__ void k_scan_write() {
    __shared__ int sm[SCAN_BLK];
    int t = threadIdx.x;
    int i = blockIdx.x * SCAN_BLK + t;
    int v = (i < NN) ? g_cnt[i] : 0;
    sm[t] = v;
    __syncthreads();
#pragma unroll
    for (int d = 1; d < SCAN_BLK; d <<= 1) {
        int u = (t >= d) ? sm[t - d] : 0;
        __syncthreads();
        sm[t] += u;
        __syncthreads();
    }
    if (i < NN) {
        int off = g_bsum[blockIdx.x] + sm[t] - v;   // exclusive prefix
        g_off[i] = off;
        g_cur[i] = off;
    }
}

__global__ void k_fill(const int* __restrict__ src, const int* __restrict__ dst) {
    int e = blockIdx.x * blockDim.x + threadIdx.x;
    if (e < NE) {
        int d = dst[e];
        int pos = atomicAdd(&g_cur[d], 1);
        g_csr[pos] = src[e];
    }
}

// ---------------- register-tiled GEMM:
// g_hs16[row][col] = (half) dinv[row] * sum_k X[row][k] * W[k][col]
template<int K, bool FROM_GH>
__global__ __launch_bounds__(256) void k_gemm(const float* __restrict__ X,
                                              const float* __restrict__ W)
{
    __shared__ float Xs[128 * 32];   // [row][kk] 16KB
    __shared__ float Ws[32 * 64];    // [kk][col]  8KB

    const float* Xp = FROM_GH ? g_h : X;
    const int tid  = threadIdx.x;
    const int row0 = blockIdx.x * 128;
    const int tx = tid & 15;         // cols tx*4 .. tx*4+3
    const int ty = tid >> 4;         // rows ty*8 .. ty*8+7

    float acc[8][4];
#pragma unroll
    for (int j = 0; j < 8; j++)
#pragma unroll
        for (int c = 0; c < 4; c++) acc[j][c] = 0.0f;

    for (int kt = 0; kt < K; kt += 32) {
#pragma unroll
        for (int i = tid; i < 1024; i += 256) {
            int r = i >> 3, f = i & 7;
            int row = row0 + r;
            float4 v = make_float4(0.f, 0.f, 0.f, 0.f);
            if (row < NN)
                v = *reinterpret_cast<const float4*>(&Xp[(size_t)row * K + kt + f * 4]);
            *reinterpret_cast<float4*>(&Xs[r * 32 + f * 4]) = v;
        }
#pragma unroll
        for (int i = tid; i < 512; i += 256) {
            int kk = i >> 4, f = i & 15;
            *reinterpret_cast<float4*>(&Ws[kk * 64 + f * 4]) =
                *reinterpret_cast<const float4*>(&W[(size_t)(kt + kk) * 64 + f * 4]);
        }
        __syncthreads();

#pragma unroll
        for (int kk = 0; kk < 32; kk++) {
            float4 wv = *reinterpret_cast<const float4*>(&Ws[kk * 64 + tx * 4]);
#pragma unroll
            for (int j = 0; j < 8; j++) {
                float xv = Xs[(ty * 8 + j) * 32 + kk];   // warp-broadcast
                acc[j][0] = fmaf(xv, wv.x, acc[j][0]);
                acc[j][1] = fmaf(xv, wv.y, acc[j][1]);
                acc[j][2] = fmaf(xv, wv.z, acc[j][2]);
                acc[j][3] = fmaf(xv, wv.w, acc[j][3]);
            }
        }
        __syncthreads();
    }

#pragma unroll
    for (int j = 0; j < 8; j++) {
        int row = row0 + ty * 8 + j;
        if (row < NN) {
            float dv = g_dinv[row];
            __half2 p0 = __floats2half2_rn(acc[j][0] * dv, acc[j][1] * dv);
            __half2 p1 = __floats2half2_rn(acc[j][2] * dv, acc[j][3] * dv);
            uint2 pk;
            pk.x = *reinterpret_cast<unsigned*>(&p0);
            pk.y = *reinterpret_cast<unsigned*>(&p1);
            *reinterpret_cast<uint2*>(&g_hs16[(size_t)row * HID + tx * 4]) = pk;
        }
    }
}

// ---------------- fp16 row accumulate helper ----------------
struct Acc8 {
    float a0 = 0.f, a1 = 0.f, a2 = 0.f, a3 = 0.f;
    float a4 = 0.f, a5 = 0.f, a6 = 0.f, a7 = 0.f;
    __device__ __forceinline__ void add(uint4 v) {
        const __half2* hp = reinterpret_cast<const __half2*>(&v);
        float2 f0 = __half22float2(hp[0]);
        float2 f1 = __half22float2(hp[1]);
        float2 f2 = __half22float2(hp[2]);
        float2 f3 = __half22float2(hp[3]);
        a0 += f0.x; a1 += f0.y; a2 += f1.x; a3 += f1.y;
        a4 += f2.x; a5 += f2.y; a6 += f3.x; a7 += f3.y;
    }
    __device__ __forceinline__ void reduce_q() {
#pragma unroll
        for (int d = 8; d <= 16; d <<= 1) {
            a0 += __shfl_xor_sync(0xffffffffu, a0, d);
            a1 += __shfl_xor_sync(0xffffffffu, a1, d);
            a2 += __shfl_xor_sync(0xffffffffu, a2, d);
            a3 += __shfl_xor_sync(0xffffffffu, a3, d);
            a4 += __shfl_xor_sync(0xffffffffu, a4, d);
            a5 += __shfl_xor_sync(0xffffffffu, a5, d);
            a6 += __shfl_xor_sync(0xffffffffu, a6, d);
            a7 += __shfl_xor_sync(0xffffffffu, a7, d);
        }
    }
};

// ---------------- layer-1 gather (fp16 hs): one warp per node.
// q = lane>>3 selects edge-of-quad, c8 = lane&7 selects 8-feature chunk.
__global__ __launch_bounds__(256) void k_gather1(const float* __restrict__ b)
{
    int w = blockIdx.x * 8 + (threadIdx.x >> 5);
    if (w >= NN) return;
    const int lane = threadIdx.x & 31;
    const int q  = lane >> 3;
    const int c8 = lane & 7;

    const int off = __ldg(&g_off[w]);
    const int cnt = __ldg(&g_cnt[w]);

    Acc8 A;
    int j = 0;
    for (; j + 4 <= cnt; j += 4) {
        int s = __ldg(&g_csr[off + j + q]);
        A.add(*reinterpret_cast<const uint4*>(&g_hs16[(size_t)s * HID + c8 * 8]));
    }
    if (j + q < cnt) {
        int s = __ldg(&g_csr[off + j + q]);
        A.add(*reinterpret_cast<const uint4*>(&g_hs16[(size_t)s * HID + c8 * 8]));
    }
    A.reduce_q();

    if (q == 0) {
        uint4 v = *reinterpret_cast<const uint4*>(&g_hs16[(size_t)w * HID + c8 * 8]);
        const __half2* hp = reinterpret_cast<const __half2*>(&v);
        float2 f0 = __half22float2(hp[0]);
        float2 f1 = __half22float2(hp[1]);
        float2 f2 = __half22float2(hp[2]);
        float2 f3 = __half22float2(hp[3]);
        float dv  = __ldg(&g_dinv[w]);
        float4 b0 = *reinterpret_cast<const float4*>(&b[c8 * 8]);
        float4 b1 = *reinterpret_cast<const float4*>(&b[c8 * 8 + 4]);

        float4 o0, o1;
        o0.x = fmaxf(fmaf(dv, A.a0 + f0.x, b0.x), 0.f);
        o0.y = fmaxf(fmaf(dv, A.a1 + f0.y, b0.y), 0.f);
        o0.z = fmaxf(fmaf(dv, A.a2 + f1.x, b0.z), 0.f);
        o0.w = fmaxf(fmaf(dv, A.a3 + f1.y, b0.w), 0.f);
        o1.x = fmaxf(fmaf(dv, A.a4 + f2.x, b1.x), 0.f);
        o1.y = fmaxf(fmaf(dv, A.a5 + f2.y, b1.y), 0.f);
        o1.z = fmaxf(fmaf(dv, A.a6 + f3.x, b1.z), 0.f);
        o1.w = fmaxf(fmaf(dv, A.a7 + f3.y, b1.w), 0.f);

        *reinterpret_cast<float4*>(&g_h[(size_t)w * HID + c8 * 8])     = o0;
        *reinterpret_cast<float4*>(&g_h[(size_t)w * HID + c8 * 8 + 4]) = o1;
    }
}

// ---------------- layer-2 gather (fp16 hs) + fused softmax head:
// 512 threads = 16 warps/block; one warp per node; same q/c8 layout.
__global__ __launch_bounds__(512) void k_gather2_head(const float* __restrict__ b,
                                                      const float* __restrict__ Wout,
                                                      const float* __restrict__ bout,
                                                      float* __restrict__ out)
{
    __shared__ float Wsm [HID * NC];   // 8KB
    __shared__ float Hrow[16 * HID];   // 4KB

    const int tid  = threadIdx.x;
    const int wid  = tid >> 5;
    const int lane = tid & 31;

    for (int i = tid; i < HID * NC; i += 512) Wsm[i] = Wout[i];
    float bo = __ldg(&bout[lane]);
    __syncthreads();

    int w = blockIdx.x * 16 + wid;
    if (w >= NN) return;               // whole warp exits together
    const int q  = lane >> 3;
    const int c8 = lane & 7;

    const int off = __ldg(&g_off[w]);
    const int cnt = __ldg(&g_cnt[w]);

    Acc8 A;
    int j = 0;
    for (; j + 4 <= cnt; j += 4) {
        int s = __ldg(&g_csr[off + j + q]);
        A.add(*reinterpret_cast<const uint4*>(&g_hs16[(size_t)s * HID + c8 * 8]));
    }
    if (j + q < cnt) {
        int s = __ldg(&g_csr[off + j + q]);
        A.add(*reinterpret_cast<const uint4*>(&g_hs16[(size_t)s * HID + c8 * 8]));
    }
    A.reduce_q();

    if (q == 0) {
        uint4 v = *reinterpret_cast<const uint4*>(&g_hs16[(size_t)w * HID + c8 * 8]);
        const __half2* hp = reinterpret_cast<const __half2*>(&v);
        float2 f0 = __half22float2(hp[0]);
        float2 f1 = __half22float2(hp[1]);
        float2 f2 = __half22float2(hp[2]);
        float2 f3 = __half22float2(hp[3]);
        float dv  = __ldg(&g_dinv[w]);
        float4 b0 = *reinterpret_cast<const float4*>(&b[c8 * 8]);
        float4 b1 = *reinterpret_cast<const float4*>(&b[c8 * 8 + 4]);

        float4 o0, o1;
        o0.x = fmaxf(fmaf(dv, A.a0 + f0.x, b0.x), 0.f);
        o0.y = fmaxf(fmaf(dv, A.a1 + f0.y, b0.y), 0.f);
        o0.z = fmaxf(fmaf(dv, A.a2 + f1.x, b0.z), 0.f);
        o0.w = fmaxf(fmaf(dv, A.a3 + f1.y, b0.w), 0.f);
        o1.x = fmaxf(fmaf(dv, A.a4 + f2.x, b1.x), 0.f);
        o1.y = fmaxf(fmaf(dv, A.a5 + f2.y, b1.y), 0.f);
        o1.z = fmaxf(fmaf(dv, A.a6 + f3.x, b1.z), 0.f);
        o1.w = fmaxf(fmaf(dv, A.a7 + f3.y, b1.w), 0.f);

        *reinterpret_cast<float4*>(&Hrow[wid * HID + c8 * 8])     = o0;
        *reinterpret_cast<float4*>(&Hrow[wid * HID + c8 * 8 + 4]) = o1;
    }
    __syncwarp();

    // logits: each lane = one class; Wsm conflict-free, Hrow broadcast
    float lg = bo;
#pragma unroll
    for (int k = 0; k < HID; k++)
        lg = fmaf(Hrow[wid * HID + k], Wsm[k * NC + lane], lg);

    // stable softmax over 32 lanes
    float m = lg;
#pragma unroll
    for (int o2 = 16; o2; o2 >>= 1)
        m = fmaxf(m, __shfl_xor_sync(0xffffffffu, m, o2));
    float ex = __expf(lg - m);
    float s = ex;
#pragma unroll
    for (int o2 = 16; o2; o2 >>= 1)
        s += __shfl_xor_sync(0xffffffffu, s, o2);

    out[(size_t)w * NC + lane] = ex / s;
}

// ---------------- stream/event handles (created once; no device mem) -----
struct ForkHandles {
    cudaStream_t s2;
    cudaEvent_t  eFork, eJoin;
    void* cntPtr;
    ForkHandles() {
        cudaStreamCreateWithFlags(&s2, cudaStreamNonBlocking);
        cudaEventCreateWithFlags(&eFork, cudaEventDisableTiming);
        cudaEventCreateWithFlags(&eJoin, cudaEventDisableTiming);
        cudaGetSymbolAddress(&cntPtr, g_cnt);
    }
};

// ---------------- launcher ----------------
extern "C" void kernel_launch(void* const* d_in, const int* in_sizes, int n_in,
                              void* d_out, int out_size)
{
    static ForkHandles fh;   // same capture structure on every call

    const float* x    = (const float*)d_in[0];
    const int*   ei   = (const int*)  d_in[1];   // [2, E]
    const float* W1   = (const float*)d_in[2];
    const float* b1   = (const float*)d_in[3];
    const float* W2   = (const float*)d_in[4];
    const float* b2   = (const float*)d_in[5];
    const float* Wout = (const float*)d_in[6];
    const float* bout = (const float*)d_in[7];
    float* out = (float*)d_out;

    const int* src = ei;
    const int* dst = ei + NE;

    const int TB = 256;
    int gN    = (NN + TB - 1) / TB;            // 391
    int gE    = (NE + TB - 1) / TB;            // 6250
    int gGemm = (NN + 127) / 128;              // 782
    int gG1   = (NN + 7) / 8;                  // 12500
    int gG2   = (NN + 15) / 16;                // 6250

    // ---- counts (needed by dinv and the CSR chain) ----
    cudaMemsetAsync(fh.cntPtr, 0, NN * sizeof(int), 0);
    k_count<<<gE, TB>>>(dst);

    // ---- fork: scan/fill chain runs parallel to dinv + GEMM1 ----
    cudaEventRecord(fh.eFork, 0);
    cudaStreamWaitEvent(fh.s2, fh.eFork, 0);

    k_scan_blocksum<<<NBS, SCAN_BLK, 0, fh.s2>>>();
    k_scan_bsum    <<<1, 256,        0, fh.s2>>>();
    k_scan_write   <<<NBS, SCAN_BLK, 0, fh.s2>>>();
    k_fill         <<<gE, TB,        0, fh.s2>>>(src, dst);
    cudaEventRecord(fh.eJoin, fh.s2);

    // main branch: dinv + layer-1 GEMM (fp16 hs, dinv-scaled)
    k_dinv<<<gN, TB>>>();
    k_gemm<FIN, false><<<gGemm, TB>>>(x, W1);

    // ---- join: gather needs GEMM1 (g_hs16) + CSR (g_off/g_csr) ----
    cudaStreamWaitEvent(0, fh.eJoin, 0);

    // layer 1 aggregation (fp16 gather, fp32 accumulate)
    k_gather1<<<gG1, TB>>>(b1);

    // layer 2 GEMM (fp16 hs) + fused gather/softmax head
    k_gemm<HID, true><<<gGemm, TB>>>(nullptr, W2);
    k_gather2_head<<<gG2, 512>>>(b2, Wout, bout, out);
}

// round 13
// speedup vs baseline: 1.1936x; 1.0922x over previous
#include <cuda_runtime.h>
#include <cuda_fp16.h>
#include <cuda_bf16.h>
#include <cstdint>

// Problem constants
#define NN   100000     // nodes
#define NE   1600000    // edges
#define FIN  128        // input features
#define HID  64         // hidden
#define NC   32         // classes

#define SCAN_BLK 512
#define NBS ((NN + SCAN_BLK - 1) / SCAN_BLK)   // 196

// ---------------- device scratch (static allocation only) ----------------
__device__ int    g_cnt [NN];        // in-degree (excl. self-loop)
__device__ int    g_off [NN];        // CSR offsets (exclusive prefix of cnt)
__device__ int    g_cur [NN];        // fill cursors
__device__ int    g_csr [NE];        // src ids grouped by dst
__device__ int    g_bsum[NBS];       // scan block sums
__device__ float  g_dinv[NN];
__device__ __half g_hs16[NN * HID];  // dinv-scaled X@W (fp16, reused both layers)
__device__ float  g_h   [NN * HID];  // relu'd layer-1 output

// ---------------- degree counting / dinv ----------------
__global__ void k_count(const int* __restrict__ dst) {
    int e = blockIdx.x * blockDim.x + threadIdx.x;
    if (e < NE) atomicAdd(&g_cnt[dst[e]], 1);
}

__global__ void k_dinv() {
    int i = blockIdx.x * blockDim.x + threadIdx.x;
    if (i < NN) g_dinv[i] = rsqrtf((float)g_cnt[i] + 1.0f);   // + self-loop
}

// ---------------- CSR build: 3-step scan + bucket fill ----------------
__global__ void k_scan_blocksum() {
    __shared__ int sm[SCAN_BLK];
    int t = threadIdx.x;
    int i = blockIdx.x * SCAN_BLK + t;
    sm[t] = (i < NN) ? g_cnt[i] : 0;
    __syncthreads();
#pragma unroll
    for (int s = SCAN_BLK / 2; s > 0; s >>= 1) {
        if (t < s) sm[t] += sm[t + s];
        __syncthreads();
    }
    if (t == 0) g_bsum[blockIdx.x] = sm[0];
}

__global__ void k_scan_bsum() {     // single block of 256, NBS=196 <= 256
    __shared__ int sm[256];
    int t = threadIdx.x;
    int orig = (t < NBS) ? g_bsum[t] : 0;
    sm[t] = orig;
    __syncthreads();
#pragma unroll
    for (int d = 1; d < 256; d <<= 1) {
        int v = (t >= d) ? sm[t - d] : 0;
        __syncthreads();
        sm[t] += v;
        __syncthreads();
    }
    if (t < NBS) g_bsum[t] = sm[t] - orig;   // exclusive
}

__global__ void k_scan_write() {
    __shared__ int sm[SCAN_BLK];
    int t = threadIdx.x;
    int i = blockIdx.x * SCAN_BLK + t;
    int v = (i < NN) ? g_cnt[i] : 0;
    sm[t] = v;
    __syncthreads();
#pragma unroll
    for (int d = 1; d < SCAN_BLK; d <<= 1) {
        int u = (t >= d) ? sm[t - d] : 0;
        __syncthreads();
        sm[t] += u;
        __syncthreads();
    }
    if (i < NN) {
        int off = g_bsum[blockIdx.x] + sm[t] - v;   // exclusive prefix
        g_off[i] = off;
        g_cur[i] = off;
    }
}

__global__ void k_fill(const int* __restrict__ src, const int* __restrict__ dst) {
    int e = blockIdx.x * blockDim.x + threadIdx.x;
    if (e < NE) {
        int d = dst[e];
        int pos = atomicAdd(&g_cur[d], 1);
        g_csr[pos] = src[e];
    }
}

// ---------------- tensor-core helpers ----------------
__device__ __forceinline__ void ldsm_x4(uint32_t& r0, uint32_t& r1,
                                        uint32_t& r2, uint32_t& r3, uint32_t a) {
    asm volatile("ldmatrix.sync.aligned.m8n8.x4.shared.b16 {%0,%1,%2,%3}, [%4];"
                 : "=r"(r0), "=r"(r1), "=r"(r2), "=r"(r3) : "r"(a));
}
__device__ __forceinline__ void ldsm_x2t(uint32_t& r0, uint32_t& r1, uint32_t a) {
    asm volatile("ldmatrix.sync.aligned.m8n8.x2.trans.shared.b16 {%0,%1}, [%2];"
                 : "=r"(r0), "=r"(r1) : "r"(a));
}
__device__ __forceinline__ void mma16816(float* c, const uint32_t* a, const uint32_t* b) {
    asm volatile(
        "mma.sync.aligned.m16n8k16.row.col.f32.f16.f16.f32 "
        "{%0,%1,%2,%3}, {%4,%5,%6,%7}, {%8,%9}, {%0,%1,%2,%3};"
        : "+f"(c[0]), "+f"(c[1]), "+f"(c[2]), "+f"(c[3])
        : "r"(a[0]), "r"(a[1]), "r"(a[2]), "r"(a[3]), "r"(b[0]), "r"(b[1]));
}

__device__ __forceinline__ uint4 pack_half8(float4 v0, float4 v1) {
    __half2 h0 = __floats2half2_rn(v0.x, v0.y);
    __half2 h1 = __floats2half2_rn(v0.z, v0.w);
    __half2 h2 = __floats2half2_rn(v1.x, v1.y);
    __half2 h3 = __floats2half2_rn(v1.z, v1.w);
    uint4 pk;
    pk.x = *reinterpret_cast<unsigned*>(&h0);
    pk.y = *reinterpret_cast<unsigned*>(&h1);
    pk.z = *reinterpret_cast<unsigned*>(&h2);
    pk.w = *reinterpret_cast<unsigned*>(&h3);
    return pk;
}

// ---------------- layer-1 GEMM on tensor cores (HMMA fp16, fp32 accum):
// g_hs16[row][col] = (half) dinv[row] * sum_k X[row][k] * W1[k][col]
// Block: 256 thr = 8 warps (4 m x 2 n). Tile 128 rows x 64 cols x K=128.
__global__ __launch_bounds__(256) void k_gemm1_tc(const float* __restrict__ X,
                                                  const float* __restrict__ W)
{
    __shared__ __align__(16) __half As[128 * 128];   // 32KB, XOR-swizzled
    __shared__ __align__(16) __half Bs[128 * 64];    // 16KB, XOR-swizzled

    const int tid  = threadIdx.x;
    const int row0 = blockIdx.x * 128;

    // X -> As: 2048 16B-chunks (8 halves); chunk (r, c): c' = c ^ (r&7)
#pragma unroll
    for (int i = tid; i < 2048; i += 256) {
        int r = i >> 4, c = i & 15;
        int row = row0 + r;
        float4 v0 = make_float4(0.f, 0.f, 0.f, 0.f), v1 = v0;
        if (row < NN) {
            v0 = *reinterpret_cast<const float4*>(&X[(size_t)row * FIN + c * 8]);
            v1 = *reinterpret_cast<const float4*>(&X[(size_t)row * FIN + c * 8 + 4]);
        }
        *reinterpret_cast<uint4*>(&As[r * 128 + ((c ^ (r & 7)) << 3)]) = pack_half8(v0, v1);
    }
    // W -> Bs: 1024 chunks; chunk (r, c in 0..7): c' = c ^ (r&7)
#pragma unroll
    for (int i = tid; i < 1024; i += 256) {
        int r = i >> 3, c = i & 7;
        float4 v0 = *reinterpret_cast<const float4*>(&W[(size_t)r * 64 + c * 8]);
        float4 v1 = *reinterpret_cast<const float4*>(&W[(size_t)r * 64 + c * 8 + 4]);
        *reinterpret_cast<uint4*>(&Bs[r * 64 + ((c ^ (r & 7)) << 3)]) = pack_half8(v0, v1);
    }
    __syncthreads();

    const int wid  = tid >> 5;
    const int lane = tid & 31;
    const int wm   = wid >> 1;        // 0..3: rows wm*32
    const int wn   = wid & 1;         // 0..1: cols wn*32

    uint32_t a_base = (uint32_t)__cvta_generic_to_shared(As);
    uint32_t b_base = (uint32_t)__cvta_generic_to_shared(Bs);

    float acc[2][4][4];
#pragma unroll
    for (int mt = 0; mt < 2; mt++)
#pragma unroll
        for (int nt = 0; nt < 4; nt++)
#pragma unroll
            for (int e = 0; e < 4; e++) acc[mt][nt][e] = 0.f;

#pragma unroll
    for (int kk = 0; kk < 8; kk++) {
        const int k0 = kk * 16;
        uint32_t afr[2][4];
#pragma unroll
        for (int mt = 0; mt < 2; mt++) {
            int r  = wm * 32 + mt * 16 + (lane & 15);
            int kh = k0 + ((lane >> 4) << 3);          // k0 or k0+8
            int ch = (kh >> 3) ^ (r & 7);
            uint32_t addr = a_base + (unsigned)(r * 256 + ch * 16);
            ldsm_x4(afr[mt][0], afr[mt][1], afr[mt][2], afr[mt][3], addr);
        }
        uint32_t bfr[4][2];
#pragma unroll
        for (int nt = 0; nt < 4; nt++) {
            int r  = k0 + (lane & 15);
            int ch = ((wn * 32 + nt * 8) >> 3) ^ (r & 7);
            uint32_t addr = b_base + (unsigned)(r * 128 + ch * 16);
            ldsm_x2t(bfr[nt][0], bfr[nt][1], addr);
        }
#pragma unroll
        for (int mt = 0; mt < 2; mt++)
#pragma unroll
            for (int nt = 0; nt < 4; nt++)
                mma16816(acc[mt][nt], afr[mt], bfr[nt]);
    }

    // epilogue: scale by dinv, convert to half, store
#pragma unroll
    for (int mt = 0; mt < 2; mt++) {
        int rlo = row0 + wm * 32 + mt * 16 + (lane >> 2);
        int rhi = rlo + 8;
        float dv0 = (rlo < NN) ? g_dinv[rlo] : 0.f;
        float dv1 = (rhi < NN) ? g_dinv[rhi] : 0.f;
#pragma unroll
        for (int nt = 0; nt < 4; nt++) {
            int col = wn * 32 + nt * 8 + ((lane & 3) << 1);
            if (rlo < NN) {
                __half2 p = __floats2half2_rn(acc[mt][nt][0] * dv0, acc[mt][nt][1] * dv0);
                *reinterpret_cast<__half2*>(&g_hs16[(size_t)rlo * HID + col]) = p;
            }
            if (rhi < NN) {
                __half2 p = __floats2half2_rn(acc[mt][nt][2] * dv1, acc[mt][nt][3] * dv1);
                *reinterpret_cast<__half2*>(&g_hs16[(size_t)rhi * HID + col]) = p;
            }
        }
    }
}

// ---------------- register-tiled FFMA GEMM (layer 2):
// g_hs16[row][col] = (half) dinv[row] * sum_k g_h[row][k] * W[k][col]
template<int K>
__global__ __launch_bounds__(256) void k_gemm(const float* __restrict__ W)
{
    __shared__ float Xs[128 * 32];   // [row][kk] 16KB
    __shared__ float Ws[32 * 64];    // [kk][col]  8KB

    const int tid  = threadIdx.x;
    const int row0 = blockIdx.x * 128;
    const int tx = tid & 15;
    const int ty = tid >> 4;

    float acc[8][4];
#pragma unroll
    for (int j = 0; j < 8; j++)
#pragma unroll
        for (int c = 0; c < 4; c++) acc[j][c] = 0.0f;

    for (int kt = 0; kt < K; kt += 32) {
#pragma unroll
        for (int i = tid; i < 1024; i += 256) {
            int r = i >> 3, f = i & 7;
            int row = row0 + r;
            float4 v = make_float4(0.f, 0.f, 0.f, 0.f);
            if (row < NN)
                v = *reinterpret_cast<const float4*>(&g_h[(size_t)row * K + kt + f * 4]);
            *reinterpret_cast<float4*>(&Xs[r * 32 + f * 4]) = v;
        }
#pragma unroll
        for (int i = tid; i < 512; i += 256) {
            int kk = i >> 4, f = i & 15;
            *reinterpret_cast<float4*>(&Ws[kk * 64 + f * 4]) =
                *reinterpret_cast<const float4*>(&W[(size_t)(kt + kk) * 64 + f * 4]);
        }
        __syncthreads();

#pragma unroll
        for (int kk = 0; kk < 32; kk++) {
            float4 wv = *reinterpret_cast<const float4*>(&Ws[kk * 64 + tx * 4]);
#pragma unroll
            for (int j = 0; j < 8; j++) {
                float xv = Xs[(ty * 8 + j) * 32 + kk];
                acc[j][0] = fmaf(xv, wv.x, acc[j][0]);
                acc[j][1] = fmaf(xv, wv.y, acc[j][1]);
                acc[j][2] = fmaf(xv, wv.z, acc[j][2]);
                acc[j][3] = fmaf(xv, wv.w, acc[j][3]);
            }
        }
        __syncthreads();
    }

#pragma unroll
    for (int j = 0; j < 8; j++) {
        int row = row0 + ty * 8 + j;
        if (row < NN) {
            float dv = g_dinv[row];
            __half2 p0 = __floats2half2_rn(acc[j][0] * dv, acc[j][1] * dv);
            __half2 p1 = __floats2half2_rn(acc[j][2] * dv, acc[j][3] * dv);
            uint2 pk;
            pk.x = *reinterpret_cast<unsigned*>(&p0);
            pk.y = *reinterpret_cast<unsigned*>(&p1);
            *reinterpret_cast<uint2*>(&g_hs16[(size_t)row * HID + tx * 4]) = pk;
        }
    }
}

// ---------------- fp16 row accumulate helper ----------------
struct Acc8 {
    float a0 = 0.f, a1 = 0.f, a2 = 0.f, a3 = 0.f;
    float a4 = 0.f, a5 = 0.f, a6 = 0.f, a7 = 0.f;
    __device__ __forceinline__ void add(uint4 v) {
        const __half2* hp = reinterpret_cast<const __half2*>(&v);
        float2 f0 = __half22float2(hp[0]);
        float2 f1 = __half22float2(hp[1]);
        float2 f2 = __half22float2(hp[2]);
        float2 f3 = __half22float2(hp[3]);
        a0 += f0.x; a1 += f0.y; a2 += f1.x; a3 += f1.y;
        a4 += f2.x; a5 += f2.y; a6 += f3.x; a7 += f3.y;
    }
    __device__ __forceinline__ void reduce_q() {
#pragma unroll
        for (int d = 8; d <= 16; d <<= 1) {
            a0 += __shfl_xor_sync(0xffffffffu, a0, d);
            a1 += __shfl_xor_sync(0xffffffffu, a1, d);
            a2 += __shfl_xor_sync(0xffffffffu, a2, d);
            a3 += __shfl_xor_sync(0xffffffffu, a3, d);
            a4 += __shfl_xor_sync(0xffffffffu, a4, d);
            a5 += __shfl_xor_sync(0xffffffffu, a5, d);
            a6 += __shfl_xor_sync(0xffffffffu, a6, d);
            a7 += __shfl_xor_sync(0xffffffffu, a7, d);
        }
    }
};

// ---------------- layer-1 gather (fp16 hs): one warp per node.
__global__ __launch_bounds__(256) void k_gather1(const float* __restrict__ b)
{
    int w = blockIdx.x * 8 + (threadIdx.x >> 5);
    if (w >= NN) return;
    const int lane = threadIdx.x & 31;
    const int q  = lane >> 3;
    const int c8 = lane & 7;

    const int off = __ldg(&g_off[w]);
    const int cnt = __ldg(&g_cnt[w]);

    Acc8 A;
    int j = 0;
    for (; j + 4 <= cnt; j += 4) {
        int s = __ldg(&g_csr[off + j + q]);
        A.add(*reinterpret_cast<const uint4*>(&g_hs16[(size_t)s * HID + c8 * 8]));
    }
    if (j + q < cnt) {
        int s = __ldg(&g_csr[off + j + q]);
        A.add(*reinterpret_cast<const uint4*>(&g_hs16[(size_t)s * HID + c8 * 8]));
    }
    A.reduce_q();

    if (q == 0) {
        uint4 v = *reinterpret_cast<const uint4*>(&g_hs16[(size_t)w * HID + c8 * 8]);
        const __half2* hp = reinterpret_cast<const __half2*>(&v);
        float2 f0 = __half22float2(hp[0]);
        float2 f1 = __half22float2(hp[1]);
        float2 f2 = __half22float2(hp[2]);
        float2 f3 = __half22float2(hp[3]);
        float dv  = __ldg(&g_dinv[w]);
        float4 b0 = *reinterpret_cast<const float4*>(&b[c8 * 8]);
        float4 b1 = *reinterpret_cast<const float4*>(&b[c8 * 8 + 4]);

        float4 o0, o1;
        o0.x = fmaxf(fmaf(dv, A.a0 + f0.x, b0.x), 0.f);
        o0.y = fmaxf(fmaf(dv, A.a1 + f0.y, b0.y), 0.f);
        o0.z = fmaxf(fmaf(dv, A.a2 + f1.x, b0.z), 0.f);
        o0.w = fmaxf(fmaf(dv, A.a3 + f1.y, b0.w), 0.f);
        o1.x = fmaxf(fmaf(dv, A.a4 + f2.x, b1.x), 0.f);
        o1.y = fmaxf(fmaf(dv, A.a5 + f2.y, b1.y), 0.f);
        o1.z = fmaxf(fmaf(dv, A.a6 + f3.x, b1.z), 0.f);
        o1.w = fmaxf(fmaf(dv, A.a7 + f3.y, b1.w), 0.f);

        *reinterpret_cast<float4*>(&g_h[(size_t)w * HID + c8 * 8])     = o0;
        *reinterpret_cast<float4*>(&g_h[(size_t)w * HID + c8 * 8 + 4]) = o1;
    }
}

// ---------------- layer-2 gather (fp16 hs) + fused softmax head ----------
__global__ __launch_bounds__(512) void k_gather2_head(const float* __restrict__ b,
                                                      const float* __restrict__ Wout,
                                                      const float* __restrict__ bout,
                                                      float* __restrict__ out)
{
    __shared__ float Wsm [HID * NC];   // 8KB
    __shared__ float Hrow[16 * HID];   // 4KB

    const int tid  = threadIdx.x;
    const int wid  = tid >> 5;
    const int lane = tid & 31;

    for (int i = tid; i < HID * NC; i += 512) Wsm[i] = Wout[i];
    float bo = __ldg(&bout[lane]);
    __syncthreads();

    int w = blockIdx.x * 16 + wid;
    if (w >= NN) return;
    const int q  = lane >> 3;
    const int c8 = lane & 7;

    const int off = __ldg(&g_off[w]);
    const int cnt = __ldg(&g_cnt[w]);

    Acc8 A;
    int j = 0;
    for (; j + 4 <= cnt; j += 4) {
        int s = __ldg(&g_csr[off + j + q]);
        A.add(*reinterpret_cast<const uint4*>(&g_hs16[(size_t)s * HID + c8 * 8]));
    }
    if (j + q < cnt) {
        int s = __ldg(&g_csr[off + j + q]);
        A.add(*reinterpret_cast<const uint4*>(&g_hs16[(size_t)s * HID + c8 * 8]));
    }
    A.reduce_q();

    if (q == 0) {
        uint4 v = *reinterpret_cast<const uint4*>(&g_hs16[(size_t)w * HID + c8 * 8]);
        const __half2* hp = reinterpret_cast<const __half2*>(&v);
        float2 f0 = __half22float2(hp[0]);
        float2 f1 = __half22float2(hp[1]);
        float2 f2 = __half22float2(hp[2]);
        float2 f3 = __half22float2(hp[3]);
        float dv  = __ldg(&g_dinv[w]);
        float4 b0 = *reinterpret_cast<const float4*>(&b[c8 * 8]);
        float4 b1 = *reinterpret_cast<const float4*>(&b[c8 * 8 + 4]);

        float4 o0, o1;
        o0.x = fmaxf(fmaf(dv, A.a0 + f0.x, b0.x), 0.f);
        o0.y = fmaxf(fmaf(dv, A.a1 + f0.y, b0.y), 0.f);
        o0.z = fmaxf(fmaf(dv, A.a2 + f1.x, b0.z), 0.f);
        o0.w = fmaxf(fmaf(dv, A.a3 + f1.y, b0.w), 0.f);
        o1.x = fmaxf(fmaf(dv, A.a4 + f2.x, b1.x), 0.f);
        o1.y = fmaxf(fmaf(dv, A.a5 + f2.y, b1.y), 0.f);
        o1.z = fmaxf(fmaf(dv, A.a6 + f3.x, b1.z), 0.f);
        o1.w = fmaxf(fmaf(dv, A.a7 + f3.y, b1.w), 0.f);

        *reinterpret_cast<float4*>(&Hrow[wid * HID + c8 * 8])     = o0;
        *reinterpret_cast<float4*>(&Hrow[wid * HID + c8 * 8 + 4]) = o1;
    }
    __syncwarp();

    float lg = bo;
#pragma unroll
    for (int k = 0; k < HID; k++)
        lg = fmaf(Hrow[wid * HID + k], Wsm[k * NC + lane], lg);

    float m = lg;
#pragma unroll
    for (int o2 = 16; o2; o2 >>= 1)
        m = fmaxf(m, __shfl_xor_sync(0xffffffffu, m, o2));
    float ex = __expf(lg - m);
    float s = ex;
#pragma unroll
    for (int o2 = 16; o2; o2 >>= 1)
        s += __shfl_xor_sync(0xffffffffu, s, o2);

    out[(size_t)w * NC + lane] = ex / s;
}

// ---------------- stream/event handles (created once; no device mem) -----
struct ForkHandles {
    cudaStream_t s2;
    cudaEvent_t  eFork, eJoin;
    void* cntPtr;
    ForkHandles() {
        cudaStreamCreateWithFlags(&s2, cudaStreamNonBlocking);
        cudaEventCreateWithFlags(&eFork, cudaEventDisableTiming);
        cudaEventCreateWithFlags(&eJoin, cudaEventDisableTiming);
        cudaGetSymbolAddress(&cntPtr, g_cnt);
    }
};

// ---------------- launcher ----------------
extern "C" void kernel_launch(void* const* d_in, const int* in_sizes, int n_in,
                              void* d_out, int out_size)
{
    static ForkHandles fh;   // same capture structure on every call

    const float* x    = (const float*)d_in[0];
    const int*   ei   = (const int*)  d_in[1];   // [2, E]
    const float* W1   = (const float*)d_in[2];
    const float* b1   = (const float*)d_in[3];
    const float* W2   = (const float*)d_in[4];
    const float* b2   = (const float*)d_in[5];
    const float* Wout = (const float*)d_in[6];
    const float* bout = (const float*)d_in[7];
    float* out = (float*)d_out;

    const int* src = ei;
    const int* dst = ei + NE;

    const int TB = 256;
    int gN    = (NN + TB - 1) / TB;            // 391
    int gE    = (NE + TB - 1) / TB;            // 6250
    int gGemm = (NN + 127) / 128;              // 782
    int gG1   = (NN + 7) / 8;                  // 12500
    int gG2   = (NN + 15) / 16;                // 6250

    // ---- counts (needed by dinv and the CSR chain) ----
    cudaMemsetAsync(fh.cntPtr, 0, NN * sizeof(int), 0);
    k_count<<<gE, TB>>>(dst);

    // ---- fork: scan/fill chain runs parallel to dinv + GEMM1 ----
    cudaEventRecord(fh.eFork, 0);
    cudaStreamWaitEvent(fh.s2, fh.eFork, 0);

    k_scan_blocksum<<<NBS, SCAN_BLK, 0, fh.s2>>>();
    k_scan_bsum    <<<1, 256,        0, fh.s2>>>();
    k_scan_write   <<<NBS, SCAN_BLK, 0, fh.s2>>>();
    k_fill         <<<gE, TB,        0, fh.s2>>>(src, dst);
    cudaEventRecord(fh.eJoin, fh.s2);

    // main branch: dinv + layer-1 tensor-core GEMM (fp16 hs, dinv-scaled)
    k_dinv<<<gN, TB>>>();
    k_gemm1_tc<<<gGemm, TB>>>(x, W1);

    // ---- join: gather needs GEMM1 (g_hs16) + CSR (g_off/g_csr) ----
    cudaStreamWaitEvent(0, fh.eJoin, 0);

    // layer 1 aggregation (fp16 gather, fp32 accumulate)
    k_gather1<<<gG1, TB>>>(b1);

    // layer 2 GEMM (FFMA fp32 in, fp16 hs out) + fused gather/softmax head
    k_gemm<HID><<<gGemm, TB>>>(W2);
    k_gather2_head<<<gG2, 512>>>(b2, Wout, bout, out);
}

// round 14
// speedup vs baseline: 1.3275x; 1.1122x over previous
#include <cuda_runtime.h>
#include <cuda_fp16.h>
#include <cuda_bf16.h>
#include <cstdint>

// Problem constants
#define NN   100000     // nodes
#define NE   1600000    // edges
#define FIN  128        // input features
#define HID  64         // hidden
#define NC   32         // classes

#define SCAN_BLK 512
#define NBS ((NN + SCAN_BLK - 1) / SCAN_BLK)   // 196

// ---------------- device scratch (static allocation only) ----------------
__device__ int    g_cnt [NN];        // in-degree (excl. self-loop)
__device__ int    g_off [NN];        // CSR offsets (exclusive prefix of cnt)
__device__ int    g_cur [NN];        // fill cursors
__device__ int    g_csr [NE];        // src ids grouped by dst
__device__ int    g_bsum[NBS];       // scan block sums
__device__ float  g_dinv[NN];
__device__ __half g_hs16[NN * HID];  // dinv-scaled X@W (fp16, reused both layers)
__device__ __half g_h16 [NN * HID];  // relu'd layer-1 output (fp16)

// ---------------- degree counting / dinv ----------------
__global__ void k_count(const int* __restrict__ dst) {
    int e = blockIdx.x * blockDim.x + threadIdx.x;
    if (e < NE) atomicAdd(&g_cnt[dst[e]], 1);
}

__global__ void k_dinv() {
    int i = blockIdx.x * blockDim.x + threadIdx.x;
    if (i < NN) g_dinv[i] = rsqrtf((float)g_cnt[i] + 1.0f);   // + self-loop
}

// ---------------- CSR build: 3-step scan + bucket fill ----------------
__global__ void k_scan_blocksum() {
    __shared__ int sm[SCAN_BLK];
    int t = threadIdx.x;
    int i = blockIdx.x * SCAN_BLK + t;
    sm[t] = (i < NN) ? g_cnt[i] : 0;
    __syncthreads();
#pragma unroll
    for (int s = SCAN_BLK / 2; s > 0; s >>= 1) {
        if (t < s) sm[t] += sm[t + s];
        __syncthreads();
    }
    if (t == 0) g_bsum[blockIdx.x] = sm[0];
}

__global__ void k_scan_bsum() {     // single block of 256, NBS=196 <= 256
    __shared__ int sm[256];
    int t = threadIdx.x;
    int orig = (t < NBS) ? g_bsum[t] : 0;
    sm[t] = orig;
    __syncthreads();
#pragma unroll
    for (int d = 1; d < 256; d <<= 1) {
        int v = (t >= d) ? sm[t - d] : 0;
        __syncthreads();
        sm[t] += v;
        __syncthreads();
    }
    if (t < NBS) g_bsum[t] = sm[t] - orig;   // exclusive
}

__global__ void k_scan_write() {
    __shared__ int sm[SCAN_BLK];
    int t = threadIdx.x;
    int i = blockIdx.x * SCAN_BLK + t;
    int v = (i < NN) ? g_cnt[i] : 0;
    sm[t] = v;
    __syncthreads();
#pragma unroll
    for (int d = 1; d < SCAN_BLK; d <<= 1) {
        int u = (t >= d) ? sm[t - d] : 0;
        __syncthreads();
        sm[t] += u;
        __syncthreads();
    }
    if (i < NN) {
        int off = g_bsum[blockIdx.x] + sm[t] - v;   // exclusive prefix
        g_off[i] = off;
        g_cur[i] = off;
    }
}

__global__ void k_fill(const int* __restrict__ src, const int* __restrict__ dst) {
    int e = blockIdx.x * blockDim.x + threadIdx.x;
    if (e < NE) {
        int d = dst[e];
        int pos = atomicAdd(&g_cur[d], 1);
        g_csr[pos] = src[e];
    }
}

// ---------------- tensor-core helpers ----------------
__device__ __forceinline__ void ldsm_x4(uint32_t& r0, uint32_t& r1,
                                        uint32_t& r2, uint32_t& r3, uint32_t a) {
    asm volatile("ldmatrix.sync.aligned.m8n8.x4.shared.b16 {%0,%1,%2,%3}, [%4];"
                 : "=r"(r0), "=r"(r1), "=r"(r2), "=r"(r3) : "r"(a));
}
__device__ __forceinline__ void ldsm_x2t(uint32_t& r0, uint32_t& r1, uint32_t a) {
    asm volatile("ldmatrix.sync.aligned.m8n8.x2.trans.shared.b16 {%0,%1}, [%2];"
                 : "=r"(r0), "=r"(r1) : "r"(a));
}
__device__ __forceinline__ void mma16816(float* c, const uint32_t* a, const uint32_t* b) {
    asm volatile(
        "mma.sync.aligned.m16n8k16.row.col.f32.f16.f16.f32 "
        "{%0,%1,%2,%3}, {%4,%5,%6,%7}, {%8,%9}, {%0,%1,%2,%3};"
        : "+f"(c[0]), "+f"(c[1]), "+f"(c[2]), "+f"(c[3])
        : "r"(a[0]), "r"(a[1]), "r"(a[2]), "r"(a[3]), "r"(b[0]), "r"(b[1]));
}

__device__ __forceinline__ uint4 pack_half8(float4 v0, float4 v1) {
    __half2 h0 = __floats2half2_rn(v0.x, v0.y);
    __half2 h1 = __floats2half2_rn(v0.z, v0.w);
    __half2 h2 = __floats2half2_rn(v1.x, v1.y);
    __half2 h3 = __floats2half2_rn(v1.z, v1.w);
    uint4 pk;
    pk.x = *reinterpret_cast<unsigned*>(&h0);
    pk.y = *reinterpret_cast<unsigned*>(&h1);
    pk.z = *reinterpret_cast<unsigned*>(&h2);
    pk.w = *reinterpret_cast<unsigned*>(&h3);
    return pk;
}

// ---------------- tensor-core GEMM (HMMA fp16 in, fp32 accum):
// g_hs16[row][col] = (half) dinv[row] * sum_k A[row][k] * W[k][col]
// A source: X (fp32, converted) when !HALF_IN, else g_h16 (fp16 direct).
// Block: 256 thr = 8 warps (4 m x 2 n). Tile 128 rows x 64 cols x K.
template<int K, bool HALF_IN>
__global__ __launch_bounds__(256) void k_gemm_tc(const float* __restrict__ X,
                                                 const float* __restrict__ W)
{
    __shared__ __align__(16) __half As[128 * K];   // XOR-swizzled
    __shared__ __align__(16) __half Bs[K * 64];    // XOR-swizzled

    const int tid  = threadIdx.x;
    const int row0 = blockIdx.x * 128;
    constexpr int CPR = K / 8;       // 16B chunks per A row

    // A -> As: 128*CPR chunks; chunk (r, c): c' = c ^ (r&7)  (c < CPR)
#pragma unroll
    for (int i = tid; i < 128 * CPR; i += 256) {
        int r = i / CPR, c = i % CPR;
        int row = row0 + r;
        uint4 pk = make_uint4(0u, 0u, 0u, 0u);
        if (row < NN) {
            if (HALF_IN) {
                pk = *reinterpret_cast<const uint4*>(&g_h16[(size_t)row * K + c * 8]);
            } else {
                float4 v0 = *reinterpret_cast<const float4*>(&X[(size_t)row * K + c * 8]);
                float4 v1 = *reinterpret_cast<const float4*>(&X[(size_t)row * K + c * 8 + 4]);
                pk = pack_half8(v0, v1);
            }
        }
        *reinterpret_cast<uint4*>(&As[r * K + (((c ^ (r & 7)) & (CPR - 1)) << 3)]) = pk;
    }
    // W -> Bs: K*8 chunks; chunk (r, c in 0..7): c' = c ^ (r&7)
#pragma unroll
    for (int i = tid; i < K * 8; i += 256) {
        int r = i >> 3, c = i & 7;
        float4 v0 = *reinterpret_cast<const float4*>(&W[(size_t)r * 64 + c * 8]);
        float4 v1 = *reinterpret_cast<const float4*>(&W[(size_t)r * 64 + c * 8 + 4]);
        *reinterpret_cast<uint4*>(&Bs[r * 64 + ((c ^ (r & 7)) << 3)]) = pack_half8(v0, v1);
    }
    __syncthreads();

    const int wid  = tid >> 5;
    const int lane = tid & 31;
    const int wm   = wid >> 1;        // 0..3: rows wm*32
    const int wn   = wid & 1;         // 0..1: cols wn*32

    uint32_t a_base = (uint32_t)__cvta_generic_to_shared(As);
    uint32_t b_base = (uint32_t)__cvta_generic_to_shared(Bs);

    float acc[2][4][4];
#pragma unroll
    for (int mt = 0; mt < 2; mt++)
#pragma unroll
        for (int nt = 0; nt < 4; nt++)
#pragma unroll
            for (int e = 0; e < 4; e++) acc[mt][nt][e] = 0.f;

#pragma unroll
    for (int kk = 0; kk < K / 16; kk++) {
        const int k0 = kk * 16;
        uint32_t afr[2][4];
#pragma unroll
        for (int mt = 0; mt < 2; mt++) {
            int r  = wm * 32 + mt * 16 + (lane & 15);
            int kh = k0 + ((lane >> 4) << 3);          // k0 or k0+8
            int ch = ((kh >> 3) ^ (r & 7)) & (CPR - 1);
            uint32_t addr = a_base + (unsigned)(r * (K * 2) + ch * 16);
            ldsm_x4(afr[mt][0], afr[mt][1], afr[mt][2], afr[mt][3], addr);
        }
        uint32_t bfr[4][2];
#pragma unroll
        for (int nt = 0; nt < 4; nt++) {
            int r  = k0 + (lane & 15);
            int ch = ((wn * 32 + nt * 8) >> 3) ^ (r & 7);
            uint32_t addr = b_base + (unsigned)(r * 128 + ch * 16);
            ldsm_x2t(bfr[nt][0], bfr[nt][1], addr);
        }
#pragma unroll
        for (int mt = 0; mt < 2; mt++)
#pragma unroll
            for (int nt = 0; nt < 4; nt++)
                mma16816(acc[mt][nt], afr[mt], bfr[nt]);
    }

    // epilogue: scale by dinv, convert to half, store
#pragma unroll
    for (int mt = 0; mt < 2; mt++) {
        int rlo = row0 + wm * 32 + mt * 16 + (lane >> 2);
        int rhi = rlo + 8;
        float dv0 = (rlo < NN) ? g_dinv[rlo] : 0.f;
        float dv1 = (rhi < NN) ? g_dinv[rhi] : 0.f;
#pragma unroll
        for (int nt = 0; nt < 4; nt++) {
            int col = wn * 32 + nt * 8 + ((lane & 3) << 1);
            if (rlo < NN) {
                __half2 p = __floats2half2_rn(acc[mt][nt][0] * dv0, acc[mt][nt][1] * dv0);
                *reinterpret_cast<__half2*>(&g_hs16[(size_t)rlo * HID + col]) = p;
            }
            if (rhi < NN) {
                __half2 p = __floats2half2_rn(acc[mt][nt][2] * dv1, acc[mt][nt][3] * dv1);
                *reinterpret_cast<__half2*>(&g_hs16[(size_t)rhi * HID + col]) = p;
            }
        }
    }
}

// ---------------- fp16 row accumulate helper ----------------
struct Acc8 {
    float a0 = 0.f, a1 = 0.f, a2 = 0.f, a3 = 0.f;
    float a4 = 0.f, a5 = 0.f, a6 = 0.f, a7 = 0.f;
    __device__ __forceinline__ void add(uint4 v) {
        const __half2* hp = reinterpret_cast<const __half2*>(&v);
        float2 f0 = __half22float2(hp[0]);
        float2 f1 = __half22float2(hp[1]);
        float2 f2 = __half22float2(hp[2]);
        float2 f3 = __half22float2(hp[3]);
        a0 += f0.x; a1 += f0.y; a2 += f1.x; a3 += f1.y;
        a4 += f2.x; a5 += f2.y; a6 += f3.x; a7 += f3.y;
    }
    __device__ __forceinline__ void reduce_q() {
#pragma unroll
        for (int d = 8; d <= 16; d <<= 1) {
            a0 += __shfl_xor_sync(0xffffffffu, a0, d);
            a1 += __shfl_xor_sync(0xffffffffu, a1, d);
            a2 += __shfl_xor_sync(0xffffffffu, a2, d);
            a3 += __shfl_xor_sync(0xffffffffu, a3, d);
            a4 += __shfl_xor_sync(0xffffffffu, a4, d);
            a5 += __shfl_xor_sync(0xffffffffu, a5, d);
            a6 += __shfl_xor_sync(0xffffffffu, a6, d);
            a7 += __shfl_xor_sync(0xffffffffu, a7, d);
        }
    }
};

// ---------------- layer-1 gather (fp16 hs): one warp per node.
// Writes relu'd layer-1 output in fp16 to g_h16.
__global__ __launch_bounds__(256) void k_gather1(const float* __restrict__ b)
{
    int w = blockIdx.x * 8 + (threadIdx.x >> 5);
    if (w >= NN) return;
    const int lane = threadIdx.x & 31;
    const int q  = lane >> 3;
    const int c8 = lane & 7;

    const int off = __ldg(&g_off[w]);
    const int cnt = __ldg(&g_cnt[w]);

    Acc8 A;
    int j = 0;
    for (; j + 4 <= cnt; j += 4) {
        int s = __ldg(&g_csr[off + j + q]);
        A.add(*reinterpret_cast<const uint4*>(&g_hs16[(size_t)s * HID + c8 * 8]));
    }
    if (j + q < cnt) {
        int s = __ldg(&g_csr[off + j + q]);
        A.add(*reinterpret_cast<const uint4*>(&g_hs16[(size_t)s * HID + c8 * 8]));
    }
    A.reduce_q();

    if (q == 0) {
        uint4 v = *reinterpret_cast<const uint4*>(&g_hs16[(size_t)w * HID + c8 * 8]);
        const __half2* hp = reinterpret_cast<const __half2*>(&v);
        float2 f0 = __half22float2(hp[0]);
        float2 f1 = __half22float2(hp[1]);
        float2 f2 = __half22float2(hp[2]);
        float2 f3 = __half22float2(hp[3]);
        float dv  = __ldg(&g_dinv[w]);
        float4 b0 = *reinterpret_cast<const float4*>(&b[c8 * 8]);
        float4 b1 = *reinterpret_cast<const float4*>(&b[c8 * 8 + 4]);

        float4 o0, o1;
        o0.x = fmaxf(fmaf(dv, A.a0 + f0.x, b0.x), 0.f);
        o0.y = fmaxf(fmaf(dv, A.a1 + f0.y, b0.y), 0.f);
        o0.z = fmaxf(fmaf(dv, A.a2 + f1.x, b0.z), 0.f);
        o0.w = fmaxf(fmaf(dv, A.a3 + f1.y, b0.w), 0.f);
        o1.x = fmaxf(fmaf(dv, A.a4 + f2.x, b1.x), 0.f);
        o1.y = fmaxf(fmaf(dv, A.a5 + f2.y, b1.y), 0.f);
        o1.z = fmaxf(fmaf(dv, A.a6 + f3.x, b1.z), 0.f);
        o1.w = fmaxf(fmaf(dv, A.a7 + f3.y, b1.w), 0.f);

        *reinterpret_cast<uint4*>(&g_h16[(size_t)w * HID + c8 * 8]) = pack_half8(o0, o1);
    }
}

// ---------------- layer-2 gather (fp16 hs) + fused softmax head ----------
__global__ __launch_bounds__(512) void k_gather2_head(const float* __restrict__ b,
                                                      const float* __restrict__ Wout,
                                                      const float* __restrict__ bout,
                                                      float* __restrict__ out)
{
    __shared__ float Wsm [HID * NC];   // 8KB
    __shared__ float Hrow[16 * HID];   // 4KB

    const int tid  = threadIdx.x;
    const int wid  = tid >> 5;
    const int lane = tid & 31;

    for (int i = tid; i < HID * NC; i += 512) Wsm[i] = Wout[i];
    float bo = __ldg(&bout[lane]);
    __syncthreads();

    int w = blockIdx.x * 16 + wid;
    if (w >= NN) return;
    const int q  = lane >> 3;
    const int c8 = lane & 7;

    const int off = __ldg(&g_off[w]);
    const int cnt = __ldg(&g_cnt[w]);

    Acc8 A;
    int j = 0;
    for (; j + 4 <= cnt; j += 4) {
        int s = __ldg(&g_csr[off + j + q]);
        A.add(*reinterpret_cast<const uint4*>(&g_hs16[(size_t)s * HID + c8 * 8]));
    }
    if (j + q < cnt) {
        int s = __ldg(&g_csr[off + j + q]);
        A.add(*reinterpret_cast<const uint4*>(&g_hs16[(size_t)s * HID + c8 * 8]));
    }
    A.reduce_q();

    if (q == 0) {
        uint4 v = *reinterpret_cast<const uint4*>(&g_hs16[(size_t)w * HID + c8 * 8]);
        const __half2* hp = reinterpret_cast<const __half2*>(&v);
        float2 f0 = __half22float2(hp[0]);
        float2 f1 = __half22float2(hp[1]);
        float2 f2 = __half22float2(hp[2]);
        float2 f3 = __half22float2(hp[3]);
        float dv  = __ldg(&g_dinv[w]);
        float4 b0 = *reinterpret_cast<const float4*>(&b[c8 * 8]);
        float4 b1 = *reinterpret_cast<const float4*>(&b[c8 * 8 + 4]);

        float4 o0, o1;
        o0.x = fmaxf(fmaf(dv, A.a0 + f0.x, b0.x), 0.f);
        o0.y = fmaxf(fmaf(dv, A.a1 + f0.y, b0.y), 0.f);
        o0.z = fmaxf(fmaf(dv, A.a2 + f1.x, b0.z), 0.f);
        o0.w = fmaxf(fmaf(dv, A.a3 + f1.y, b0.w), 0.f);
        o1.x = fmaxf(fmaf(dv, A.a4 + f2.x, b1.x), 0.f);
        o1.y = fmaxf(fmaf(dv, A.a5 + f2.y, b1.y), 0.f);
        o1.z = fmaxf(fmaf(dv, A.a6 + f3.x, b1.z), 0.f);
        o1.w = fmaxf(fmaf(dv, A.a7 + f3.y, b1.w), 0.f);

        *reinterpret_cast<float4*>(&Hrow[wid * HID + c8 * 8])     = o0;
        *reinterpret_cast<float4*>(&Hrow[wid * HID + c8 * 8 + 4]) = o1;
    }
    __syncwarp();

    float lg = bo;
#pragma unroll
    for (int k = 0; k < HID; k++)
        lg = fmaf(Hrow[wid * HID + k], Wsm[k * NC + lane], lg);

    float m = lg;
#pragma unroll
    for (int o2 = 16; o2; o2 >>= 1)
        m = fmaxf(m, __shfl_xor_sync(0xffffffffu, m, o2));
    float ex = __expf(lg - m);
    float s = ex;
#pragma unroll
    for (int o2 = 16; o2; o2 >>= 1)
        s += __shfl_xor_sync(0xffffffffu, s, o2);

    out[(size_t)w * NC + lane] = ex / s;
}

// ---------------- stream/event handles (created once; no device mem) -----
struct ForkHandles {
    cudaStream_t s2;
    cudaEvent_t  eFork, eJoin;
    void* cntPtr;
    ForkHandles() {
        cudaStreamCreateWithFlags(&s2, cudaStreamNonBlocking);
        cudaEventCreateWithFlags(&eFork, cudaEventDisableTiming);
        cudaEventCreateWithFlags(&eJoin, cudaEventDisableTiming);
        cudaGetSymbolAddress(&cntPtr, g_cnt);
    }
};

// ---------------- launcher ----------------
extern "C" void kernel_launch(void* const* d_in, const int* in_sizes, int n_in,
                              void* d_out, int out_size)
{
    static ForkHandles fh;   // same capture structure on every call

    const float* x    = (const float*)d_in[0];
    const int*   ei   = (const int*)  d_in[1];   // [2, E]
    const float* W1   = (const float*)d_in[2];
    const float* b1   = (const float*)d_in[3];
    const float* W2   = (const float*)d_in[4];
    const float* b2   = (const float*)d_in[5];
    const float* Wout = (const float*)d_in[6];
    const float* bout = (const float*)d_in[7];
    float* out = (float*)d_out;

    const int* src = ei;
    const int* dst = ei + NE;

    const int TB = 256;
    int gN    = (NN + TB - 1) / TB;            // 391
    int gE    = (NE + TB - 1) / TB;            // 6250
    int gGemm = (NN + 127) / 128;              // 782
    int gG1   = (NN + 7) / 8;                  // 12500
    int gG2   = (NN + 15) / 16;                // 6250

    // ---- counts (needed by dinv and the CSR chain) ----
    cudaMemsetAsync(fh.cntPtr, 0, NN * sizeof(int), 0);
    k_count<<<gE, TB>>>(dst);

    // ---- fork: scan/fill chain runs parallel to dinv + GEMM1 ----
    cudaEventRecord(fh.eFork, 0);
    cudaStreamWaitEvent(fh.s2, fh.eFork, 0);

    k_scan_blocksum<<<NBS, SCAN_BLK, 0, fh.s2>>>();
    k_scan_bsum    <<<1, 256,        0, fh.s2>>>();
    k_scan_write   <<<NBS, SCAN_BLK, 0, fh.s2>>>();
    k_fill         <<<gE, TB,        0, fh.s2>>>(src, dst);
    cudaEventRecord(fh.eJoin, fh.s2);

    // main branch: dinv + layer-1 tensor-core GEMM (fp16 hs, dinv-scaled)
    k_dinv<<<gN, TB>>>();
    k_gemm_tc<FIN, false><<<gGemm, TB>>>(x, W1);

    // ---- join: gather needs GEMM1 (g_hs16) + CSR (g_off/g_csr) ----
    cudaStreamWaitEvent(0, fh.eJoin, 0);

    // layer 1 aggregation (fp16 gather, fp32 accumulate, fp16 out)
    k_gather1<<<gG1, TB>>>(b1);

    // layer 2 tensor-core GEMM (fp16 in/out) + fused gather/softmax head
    k_gemm_tc<HID, true><<<gGemm, TB>>>(nullptr, W2);
    k_gather2_head<<<gG2, 512>>>(b2, Wout, bout, out);
}